// round 1
// baseline (speedup 1.0000x reference)
#include <cuda_runtime.h>
#include <math.h>

#define BB 8
#define LL 512
#define DM 1024
#define NH 16
#define HD 64
#define BH (BB*NH)     // 128
#define L2 (2*LL)      // 1024

// ---- scratch (device globals: allocation-free rule) ----
__device__ float g_q[(size_t)BH*LL*HD];     // 16 MB  (b,h,l,d)
__device__ float g_v[(size_t)BH*LL*HD];     // 16 MB
__device__ float g_pos[(size_t)L2*HD];      // 256 KB (2L, 64)
__device__ float g_Dt[(size_t)NH*L2];       // 64 KB  (h, 2L)
__device__ float g_AC[(size_t)BH*LL*LL];    // 128 MB (b,h,q,k)
__device__ float g_Bf[(size_t)BH*LL*L2];    // 256 MB (b,h,q,2L)

// ---------------------------------------------------------------------------
// pos[l][d]:  l in [0,2L), p = l-L;  d<32: sin(p*invf[d]); d>=32: cos(p*invf[d-32])
// invf[i] = exp(-i * ln(10000)/31)
// ---------------------------------------------------------------------------
__global__ void pos_kernel() {
    int l = blockIdx.x;          // 0..1023
    int d = threadIdx.x;         // 0..63
    float p = (float)(l - LL);
    int i = d & 31;
    float invf = expf(-(float)i * (logf(10000.0f) / 31.0f));
    float ang = p * invf;
    g_pos[l * HD + d] = (d < 32) ? sinf(ang) : cosf(ang);
}

// D[h][l] = sum_d rw[h][d] * pos[l][d]
__global__ void dterm_kernel(const float* __restrict__ rw) {
    __shared__ float ps[HD];
    int l = blockIdx.x;
    if (threadIdx.x < HD) ps[threadIdx.x] = g_pos[l * HD + threadIdx.x];
    __syncthreads();
    if (threadIdx.x < NH) {
        int h = threadIdx.x;
        float s = 0.f;
        #pragma unroll
        for (int d = 0; d < HD; d++) s += rw[h * HD + d] * ps[d];
        g_Dt[h * L2 + l] = s;
    }
}

// ---------------------------------------------------------------------------
// qv GEMM: C[m][n] = sum_k X[m][k] * W[k][n], M=4096, N=2048, K=1024
// 128x128 tile, BK=8, 256 threads, 8x8 micro-tile (2x2 groups of 4x4).
// Epilogue scatters into g_q (n<1024) / g_v (n>=1024) in (b,h,l,d) layout.
// ---------------------------------------------------------------------------
__global__ __launch_bounds__(256) void qv_gemm(const float* __restrict__ X,
                                               const float* __restrict__ W) {
    __shared__ float As[8][132];
    __shared__ float Bs[8][132];
    int n0 = blockIdx.x * 128;
    int m0 = blockIdx.y * 128;
    int t  = threadIdx.x;
    int tx = t & 15, ty = t >> 4;
    int arow = t >> 1,  acol = (t & 1) * 4;
    int brow = t >> 5,  bcol = (t & 31) * 4;

    float acc[8][8];
    #pragma unroll
    for (int i = 0; i < 8; i++)
        #pragma unroll
        for (int j = 0; j < 8; j++) acc[i][j] = 0.f;

    const float* Ag = X + (size_t)(m0 + arow) * 1024 + acol;
    const float* Bg = W + (size_t)brow * 2048 + n0 + bcol;

    for (int k0 = 0; k0 < 1024; k0 += 8) {
        float4 av = *(const float4*)(Ag + k0);
        float4 bv = *(const float4*)(Bg + (size_t)k0 * 2048);
        As[acol + 0][arow] = av.x;
        As[acol + 1][arow] = av.y;
        As[acol + 2][arow] = av.z;
        As[acol + 3][arow] = av.w;
        *(float4*)&Bs[brow][bcol] = bv;
        __syncthreads();

        #pragma unroll
        for (int kk = 0; kk < 8; kk++) {
            float4 a0 = *(const float4*)&As[kk][ty * 4];
            float4 a1 = *(const float4*)&As[kk][64 + ty * 4];
            float4 b0 = *(const float4*)&Bs[kk][tx * 4];
            float4 b1 = *(const float4*)&Bs[kk][64 + tx * 4];
            float a[8] = {a0.x, a0.y, a0.z, a0.w, a1.x, a1.y, a1.z, a1.w};
            float b[8] = {b0.x, b0.y, b0.z, b0.w, b1.x, b1.y, b1.z, b1.w};
            #pragma unroll
            for (int i = 0; i < 8; i++)
                #pragma unroll
                for (int j = 0; j < 8; j++)
                    acc[i][j] = fmaf(a[i], b[j], acc[i][j]);
        }
        __syncthreads();
    }

    // epilogue: scatter to g_q / g_v
    #pragma unroll
    for (int i = 0; i < 8; i++) {
        int m = m0 + ((i < 4) ? (ty * 4 + i) : (64 + ty * 4 + i - 4));
        int b_ = m >> 9;          // batch
        int l  = m & 511;
        #pragma unroll
        for (int jg = 0; jg < 2; jg++) {
            int n = n0 + jg * 64 + tx * 4;
            float4 val = make_float4(acc[i][jg * 4 + 0], acc[i][jg * 4 + 1],
                                     acc[i][jg * 4 + 2], acc[i][jg * 4 + 3]);
            float* dst;
            if (n < 1024) {
                int h = n >> 6, d = n & 63;
                dst = &g_q[(((size_t)(b_ * 16 + h) * 512) + l) * 64 + d];
            } else {
                int n2 = n - 1024;
                int h = n2 >> 6, d = n2 & 63;
                dst = &g_v[(((size_t)(b_ * 16 + h) * 512) + l) * 64 + d];
            }
            *(float4*)dst = val;
        }
    }
}

// ---------------------------------------------------------------------------
// AC GEMM (NT): AC[bh][m][n] = sum_d (q[bh][m][d] + rr[h][d]) * x[b][n][h*64+d]
// 64x64 tile, BK=16, 256 threads, 4x4 micro-tile. K=64.
// ---------------------------------------------------------------------------
__global__ __launch_bounds__(256) void ac_gemm(const float* __restrict__ X,
                                               const float* __restrict__ rr) {
    __shared__ float As[16][68];
    __shared__ float Bs[16][68];
    int bh = blockIdx.z;
    int b_ = bh >> 4, h = bh & 15;
    int m0 = blockIdx.y * 64, n0 = blockIdx.x * 64;
    int t = threadIdx.x;
    int tx = t & 15, ty = t >> 4;
    int arow = t >> 2, acol = (t & 3) * 4;

    const float* Aq = g_q + (size_t)bh * LL * HD;
    const float* Bx = X + (size_t)b_ * LL * DM + h * HD;

    float acc[4][4];
    #pragma unroll
    for (int i = 0; i < 4; i++)
        #pragma unroll
        for (int j = 0; j < 4; j++) acc[i][j] = 0.f;

    for (int k0 = 0; k0 < 64; k0 += 16) {
        float4 av = *(const float4*)(Aq + (size_t)(m0 + arow) * 64 + k0 + acol);
        float4 rv = *(const float4*)(rr + h * 64 + k0 + acol);
        av.x += rv.x; av.y += rv.y; av.z += rv.z; av.w += rv.w;
        As[acol + 0][arow] = av.x;
        As[acol + 1][arow] = av.y;
        As[acol + 2][arow] = av.z;
        As[acol + 3][arow] = av.w;
        float4 bv = *(const float4*)(Bx + (size_t)(n0 + arow) * 1024 + k0 + acol);
        Bs[acol + 0][arow] = bv.x;
        Bs[acol + 1][arow] = bv.y;
        Bs[acol + 2][arow] = bv.z;
        Bs[acol + 3][arow] = bv.w;
        __syncthreads();

        #pragma unroll
        for (int kk = 0; kk < 16; kk++) {
            float4 a = *(const float4*)&As[kk][ty * 4];
            float4 b = *(const float4*)&Bs[kk][tx * 4];
            float aa[4] = {a.x, a.y, a.z, a.w};
            float bb[4] = {b.x, b.y, b.z, b.w};
            #pragma unroll
            for (int i = 0; i < 4; i++)
                #pragma unroll
                for (int j = 0; j < 4; j++)
                    acc[i][j] = fmaf(aa[i], bb[j], acc[i][j]);
        }
        __syncthreads();
    }

    float* Cp = g_AC + (size_t)bh * LL * LL;
    #pragma unroll
    for (int i = 0; i < 4; i++) {
        float4 val = make_float4(acc[i][0], acc[i][1], acc[i][2], acc[i][3]);
        *(float4*)(Cp + (size_t)(m0 + ty * 4 + i) * 512 + n0 + tx * 4) = val;
    }
}

// ---------------------------------------------------------------------------
// Bfull GEMM (NT): Bf[bh][m][n] = sum_d q[bh][m][d] * pos[n][d]  + Dt[h][n]
// M=512, N=1024, K=64.
// ---------------------------------------------------------------------------
__global__ __launch_bounds__(256) void bfull_gemm() {
    __shared__ float As[16][68];
    __shared__ float Bs[16][68];
    int bh = blockIdx.z;
    int h = bh & 15;
    int m0 = blockIdx.y * 64, n0 = blockIdx.x * 64;
    int t = threadIdx.x;
    int tx = t & 15, ty = t >> 4;
    int arow = t >> 2, acol = (t & 3) * 4;

    const float* Aq = g_q + (size_t)bh * LL * HD;

    float acc[4][4];
    #pragma unroll
    for (int i = 0; i < 4; i++)
        #pragma unroll
        for (int j = 0; j < 4; j++) acc[i][j] = 0.f;

    for (int k0 = 0; k0 < 64; k0 += 16) {
        float4 av = *(const float4*)(Aq + (size_t)(m0 + arow) * 64 + k0 + acol);
        As[acol + 0][arow] = av.x;
        As[acol + 1][arow] = av.y;
        As[acol + 2][arow] = av.z;
        As[acol + 3][arow] = av.w;
        float4 bv = *(const float4*)(g_pos + (size_t)(n0 + arow) * 64 + k0 + acol);
        Bs[acol + 0][arow] = bv.x;
        Bs[acol + 1][arow] = bv.y;
        Bs[acol + 2][arow] = bv.z;
        Bs[acol + 3][arow] = bv.w;
        __syncthreads();

        #pragma unroll
        for (int kk = 0; kk < 16; kk++) {
            float4 a = *(const float4*)&As[kk][ty * 4];
            float4 b = *(const float4*)&Bs[kk][tx * 4];
            float aa[4] = {a.x, a.y, a.z, a.w};
            float bb[4] = {b.x, b.y, b.z, b.w};
            #pragma unroll
            for (int i = 0; i < 4; i++)
                #pragma unroll
                for (int j = 0; j < 4; j++)
                    acc[i][j] = fmaf(aa[i], bb[j], acc[i][j]);
        }
        __syncthreads();
    }

    float* Cp = g_Bf + (size_t)bh * LL * L2;
    #pragma unroll
    for (int i = 0; i < 4; i++) {
        int n = n0 + tx * 4;
        float4 val = make_float4(acc[i][0] + g_Dt[h * L2 + n + 0],
                                 acc[i][1] + g_Dt[h * L2 + n + 1],
                                 acc[i][2] + g_Dt[h * L2 + n + 2],
                                 acc[i][3] + g_Dt[h * L2 + n + 3]);
        *(float4*)(Cp + (size_t)(m0 + ty * 4 + i) * 1024 + n) = val;
    }
}

// ---------------------------------------------------------------------------
// Fused gather + mask + softmax + P@V.
// Block: one (b,h), 16 query rows, 256 threads.
// scores[q][k] = AC[q][k] + Bf[q][512+k-q];  s*=mask[b][k];  s==0 -> -inf
// ---------------------------------------------------------------------------
__global__ __launch_bounds__(256) void attn_softmax_pv(const float* __restrict__ mask,
                                                       float* __restrict__ out) {
    __shared__ float sc[16][512];   // 32 KB
    __shared__ float vs[32][64];    // 8 KB
    int bh = blockIdx.x >> 5;
    int qt = blockIdx.x & 31;
    int b_ = bh >> 4, h = bh & 15;
    int q0 = qt * 16;
    int t = threadIdx.x;

    const float* ACp = g_AC + (size_t)bh * LL * LL;
    const float* Bfp = g_Bf + (size_t)bh * LL * L2;

    // phase 1: gather scores
    for (int idx = t; idx < 16 * 512; idx += 256) {
        int qi = idx >> 9, k = idx & 511;
        int q = q0 + qi;
        float s = ACp[(size_t)q * 512 + k] + Bfp[(size_t)q * 1024 + 512 + k - q];
        s *= mask[b_ * 512 + k];
        if (s == 0.0f) s = -INFINITY;
        sc[qi][k] = s;
    }
    __syncthreads();

    // phase 2: softmax, 16 threads per row (2 rows per warp, shfl width 16)
    {
        int qi = t >> 4, lane = t & 15;
        float mx = -INFINITY;
        for (int k = lane; k < 512; k += 16) mx = fmaxf(mx, sc[qi][k]);
        #pragma unroll
        for (int o = 8; o; o >>= 1) mx = fmaxf(mx, __shfl_xor_sync(0xffffffffu, mx, o, 16));
        float sum = 0.f;
        for (int k = lane; k < 512; k += 16) {
            float e = expf(sc[qi][k] - mx);
            sc[qi][k] = e;
            sum += e;
        }
        #pragma unroll
        for (int o = 8; o; o >>= 1) sum += __shfl_xor_sync(0xffffffffu, sum, o, 16);
        float inv = 1.f / sum;
        for (int k = lane; k < 512; k += 16) sc[qi][k] *= inv;
    }
    __syncthreads();

    // phase 3: P @ V, each thread owns (qi in {qg, qg+4, qg+8, qg+12}, d)
    int d = t & 63, qg = t >> 6;
    float acc[4] = {0.f, 0.f, 0.f, 0.f};
    const float* Vp = g_v + (size_t)bh * LL * HD;
    for (int kc = 0; kc < 512; kc += 32) {
        #pragma unroll
        for (int i = 0; i < 2; i++) {
            int id = t + 256 * i;
            int r = id >> 4, c4 = (id & 15) * 4;
            *(float4*)&vs[r][c4] = *(const float4*)(Vp + (size_t)(kc + r) * 64 + c4);
        }
        __syncthreads();
        #pragma unroll 8
        for (int kk = 0; kk < 32; kk++) {
            float vv = vs[kk][d];
            #pragma unroll
            for (int j = 0; j < 4; j++)
                acc[j] = fmaf(sc[qg + 4 * j][kc + kk], vv, acc[j]);
        }
        __syncthreads();
    }
    #pragma unroll
    for (int j = 0; j < 4; j++) {
        int q = q0 + qg + 4 * j;
        out[((size_t)(b_ * 512 + q)) * 1024 + h * 64 + d] = acc[j];
    }
}

// ---------------------------------------------------------------------------
extern "C" void kernel_launch(void* const* d_in, const int* in_sizes, int n_in,
                              void* d_out, int out_size) {
    const float* x    = (const float*)d_in[0];  // (8,512,1024)
    const float* mask = (const float*)d_in[1];  // (8,512)
    const float* W    = (const float*)d_in[2];  // (1024,2048)
    const float* rr   = (const float*)d_in[3];  // r_r_bias (16,64)
    const float* rw   = (const float*)d_in[4];  // r_w_bias (16,64)
    float* out = (float*)d_out;                 // (8,512,1024)

    pos_kernel<<<1024, 64>>>();
    dterm_kernel<<<1024, 64>>>(rw);
    qv_gemm<<<dim3(16, 32), 256>>>(x, W);
    ac_gemm<<<dim3(8, 8, 128), 256>>>(x, rr);
    bfull_gemm<<<dim3(16, 8, 128), 256>>>();
    attn_softmax_pv<<<4096, 256>>>(mask, out);
}

// round 2
// speedup vs baseline: 1.7821x; 1.7821x over previous
#include <cuda_runtime.h>
#include <math.h>
#include <stdint.h>

#define BB 8
#define LL 512
#define DM 1024
#define NH 16
#define HD 64
#define BH (BB*NH)     // 128

// ---- scratch (device globals; allocation-free rule) ----
__device__ float g_q [(size_t)BH*LL*HD];     // 16 MB  (bh,l,d)
__device__ float g_v [(size_t)BH*LL*HD];     // 16 MB
__device__ float g_qe[(size_t)BH*LL*128];    // 32 MB  (bh,l,128)
__device__ float g_rot[(size_t)LL*64];       // 128 KB: [k][i<32]=sin(k w_i), [32+i]=cos

// ---------------------------------------------------------------------------
// rot table: w_i = exp(-i*ln(10000)/31), i<32
// ---------------------------------------------------------------------------
__global__ void rot_kernel() {
    int k = blockIdx.x;         // 0..511
    int d = threadIdx.x;        // 0..63
    int i = d & 31;
    float w = expf(-(float)i * (logf(10000.0f) / 31.0f));
    float ang = (float)k * w;
    g_rot[k * 64 + d] = (d < 32) ? sinf(ang) : cosf(ang);
}

// ---------------------------------------------------------------------------
// qv GEMM, tf32 mma.sync: C[m][n] = sum_k X[m][k]*W[k][n], M=4096,N=2048,K=1024
// 128x128 tile, BK=32, 8 warps (4x2), each warp 32x64 via m16n8k8.
// ---------------------------------------------------------------------------
__device__ __forceinline__ uint32_t f2tf32(float x) {
    uint32_t r;
    asm("cvt.rna.tf32.f32 %0, %1;" : "=r"(r) : "f"(x));
    return r;
}
__device__ __forceinline__ void mma_tf32(float* c, const uint32_t* a, const uint32_t* b) {
    asm volatile(
        "mma.sync.aligned.m16n8k8.row.col.f32.tf32.tf32.f32 "
        "{%0,%1,%2,%3}, {%4,%5,%6,%7}, {%8,%9}, {%0,%1,%2,%3};\n"
        : "+f"(c[0]), "+f"(c[1]), "+f"(c[2]), "+f"(c[3])
        : "r"(a[0]), "r"(a[1]), "r"(a[2]), "r"(a[3]), "r"(b[0]), "r"(b[1]));
}

__global__ __launch_bounds__(256) void qv_gemm_tf32(const float* __restrict__ X,
                                                    const float* __restrict__ W) {
    __shared__ uint32_t As[128][36];   // [m][k], pad 4
    __shared__ uint32_t Bs[32][136];   // [k][n], pad 8
    int t = threadIdx.x, lane = t & 31, warp = t >> 5;
    int m0 = blockIdx.y * 128, n0 = blockIdx.x * 128;
    int wm = (warp >> 1) * 32, wn = (warp & 1) * 64;

    float c[2][8][4];
    #pragma unroll
    for (int mt = 0; mt < 2; mt++)
        #pragma unroll
        for (int nt = 0; nt < 8; nt++)
            #pragma unroll
            for (int j = 0; j < 4; j++) c[mt][nt][j] = 0.f;

    for (int k0 = 0; k0 < 1024; k0 += 32) {
        // A: 128x32 = 1024 float4, 4 per thread
        #pragma unroll
        for (int r = 0; r < 4; r++) {
            int idx = t + 256 * r;
            int m = idx >> 3, k4 = (idx & 7) * 4;
            float4 v = *(const float4*)&X[(size_t)(m0 + m) * 1024 + k0 + k4];
            uint4 u = make_uint4(f2tf32(v.x), f2tf32(v.y), f2tf32(v.z), f2tf32(v.w));
            *(uint4*)&As[m][k4] = u;
        }
        // B: 32x128 = 1024 float4, 4 per thread
        #pragma unroll
        for (int r = 0; r < 4; r++) {
            int idx = t + 256 * r;
            int k = idx >> 5, n4 = (idx & 31) * 4;
            float4 v = *(const float4*)&W[(size_t)(k0 + k) * 2048 + n0 + n4];
            uint4 u = make_uint4(f2tf32(v.x), f2tf32(v.y), f2tf32(v.z), f2tf32(v.w));
            *(uint4*)&Bs[k][n4] = u;
        }
        __syncthreads();

        #pragma unroll
        for (int k8 = 0; k8 < 4; k8++) {
            uint32_t a[2][4];
            #pragma unroll
            for (int mt = 0; mt < 2; mt++) {
                int r = wm + mt * 16 + (lane >> 2);
                int kk = k8 * 8 + (lane & 3);
                a[mt][0] = As[r][kk];
                a[mt][1] = As[r + 8][kk];
                a[mt][2] = As[r][kk + 4];
                a[mt][3] = As[r + 8][kk + 4];
            }
            #pragma unroll
            for (int nt = 0; nt < 8; nt++) {
                int kk = k8 * 8 + (lane & 3);
                int n = wn + nt * 8 + (lane >> 2);
                uint32_t b[2];
                b[0] = Bs[kk][n];
                b[1] = Bs[kk + 4][n];
                mma_tf32(c[0][nt], a[0], b);
                mma_tf32(c[1][nt], a[1], b);
            }
        }
        __syncthreads();
    }

    // epilogue: scatter into g_q / g_v, float2 stores
    #pragma unroll
    for (int mt = 0; mt < 2; mt++) {
        #pragma unroll
        for (int nt = 0; nt < 8; nt++) {
            int r0 = m0 + wm + mt * 16 + (lane >> 2);
            int cc = n0 + wn + nt * 8 + 2 * (lane & 3);
            #pragma unroll
            for (int half = 0; half < 2; half++) {
                int m = r0 + half * 8;
                float2 val = make_float2(c[mt][nt][half * 2], c[mt][nt][half * 2 + 1]);
                int b_ = m >> 9, l = m & 511;
                if (cc < 1024) {
                    int h = cc >> 6, d = cc & 63;
                    *(float2*)&g_q[(((size_t)(b_ * 16 + h) * 512) + l) * 64 + d] = val;
                } else {
                    int n2 = cc - 1024;
                    int h = n2 >> 6, d = n2 & 63;
                    *(float2*)&g_v[(((size_t)(b_ * 16 + h) * 512) + l) * 64 + d] = val;
                }
            }
        }
    }
}

// ---------------------------------------------------------------------------
// Qe build: Qe[bh][q][0:64] = q + rr[h]; Qe[64+j] = rot_q(q + rw[h])[j]
// rot(u)[i]    = u[i]*cosQ_i + u[32+i]*sinQ_i          (i<32)
// rot(u)[32+i] = u[32+i]*cosQ_i - u[i]*sinQ_i
// ---------------------------------------------------------------------------
__global__ __launch_bounds__(256) void qe_build(const float* __restrict__ rr,
                                                const float* __restrict__ rw) {
    __shared__ float u[4][64];
    int bh = blockIdx.x, h = bh & 15;
    int row = threadIdx.x >> 6;      // 0..3
    int d = threadIdx.x & 63;
    int q = blockIdx.y * 4 + row;

    float qv = g_q[((size_t)bh * 512 + q) * 64 + d];
    float outA = qv + rr[h * 64 + d];
    float uu = qv + rw[h * 64 + d];
    u[row][d] = uu;
    __syncthreads();
    int i = d & 31;
    float sq = g_rot[q * 64 + i];
    float cq = g_rot[q * 64 + 32 + i];
    float partner = u[row][d ^ 32];
    float outB = uu * cq + ((d < 32) ? partner : -partner) * sq;
    float* dst = &g_qe[((size_t)bh * 512 + q) * 128];
    dst[d] = outA;
    dst[64 + d] = outB;
}

// ---------------------------------------------------------------------------
// Fused flash attention per (b,h): S = Qe . Ke^T (K=128), online softmax, P.V
// Ke[k][0:64] = x[b,k,h*64:..]; Ke[k][64:128] = g_rot[k]
// q-tile 64, k-tile 64, 256 threads (tx=k/d dim 16, ty=q dim 16), 4x4 micro.
// smem: Qs[128x64 swz] Ks[128x64 swz, Ps aliased] Vs[64x68] ms[512]
// ---------------------------------------------------------------------------
__device__ __forceinline__ int swz(int r, int c) {   // phys word within 64-wide row
    return r * 64 + (c ^ (((r >> 2) & 15) << 2));
}

__global__ __launch_bounds__(256) void flash_attn(const float* __restrict__ X,
                                                  const float* __restrict__ mask,
                                                  float* __restrict__ out) {
    extern __shared__ float sm[];
    float* Qs = sm;                                   // 8192
    float* Ks = sm + 8192;                            // 8192
    float (*Vs)[68] = (float (*)[68])(sm + 16384);    // 64*68 = 4352
    float* ms = sm + 16384 + 64 * 68;                 // 512
    float (*Ps)[68] = (float (*)[68])Ks;              // alias (4352 <= 8192)

    int qt = blockIdx.x, bh = blockIdx.y;
    int b = bh >> 4, h = bh & 15;
    int q0 = qt * 64;
    int t = threadIdx.x, tx = t & 15, ty = t >> 4;

    // mask row
    ms[t] = mask[b * 512 + t];
    ms[t + 256] = mask[b * 512 + t + 256];

    // Qs: transposed [c][q], swizzled
    #pragma unroll
    for (int r = 0; r < 8; r++) {
        int idx = t + 256 * r;
        int q = idx >> 5, c4 = (idx & 31) * 4;
        float4 v = *(const float4*)&g_qe[((size_t)bh * 512 + q0 + q) * 128 + c4];
        float vv[4] = {v.x, v.y, v.z, v.w};
        #pragma unroll
        for (int j = 0; j < 4; j++) Qs[swz(c4 + j, q)] = vv[j];
    }

    float o[4][4], m_run[4], l_run[4];
    #pragma unroll
    for (int i = 0; i < 4; i++) {
        m_run[i] = -1e30f; l_run[i] = 0.f;
        #pragma unroll
        for (int j = 0; j < 4; j++) o[i][j] = 0.f;
    }

    for (int k0 = 0; k0 < 512; k0 += 64) {
        __syncthreads();   // protect Ks(/Ps)/Vs against previous iteration readers
        // Ks: transposed [c][k], swizzled; c<64 from x, c>=64 from rot table
        #pragma unroll
        for (int r = 0; r < 8; r++) {
            int idx = t + 256 * r;
            int k = idx >> 5, c4 = (idx & 31) * 4;
            float4 v;
            if (c4 < 64)
                v = *(const float4*)&X[((size_t)(b * 512 + k0 + k)) * 1024 + h * 64 + c4];
            else
                v = *(const float4*)&g_rot[(size_t)(k0 + k) * 64 + c4 - 64];
            float vv[4] = {v.x, v.y, v.z, v.w};
            #pragma unroll
            for (int j = 0; j < 4; j++) Ks[swz(c4 + j, k)] = vv[j];
        }
        // Vs: natural [k][d]
        #pragma unroll
        for (int r = 0; r < 4; r++) {
            int idx = t + 256 * r;
            int k = idx >> 4, d4 = (idx & 15) * 4;
            *(float4*)&Vs[k][d4] =
                *(const float4*)&g_v[((size_t)bh * 512 + k0 + k) * 64 + d4];
        }
        __syncthreads();

        // S tile: 64x64, K=128
        float s[4][4];
        #pragma unroll
        for (int i = 0; i < 4; i++)
            #pragma unroll
            for (int j = 0; j < 4; j++) s[i][j] = 0.f;

        #pragma unroll 4
        for (int kk = 0; kk < 128; kk++) {
            float4 a = *(const float4*)&Qs[swz(kk, ty * 4)];
            float4 bb = *(const float4*)&Ks[swz(kk, tx * 4)];
            float aa[4] = {a.x, a.y, a.z, a.w};
            float bv[4] = {bb.x, bb.y, bb.z, bb.w};
            #pragma unroll
            for (int i = 0; i < 4; i++)
                #pragma unroll
                for (int j = 0; j < 4; j++)
                    s[i][j] = fmaf(aa[i], bv[j], s[i][j]);
        }

        // mask + online softmax stats (16-thread row groups)
        float mk[4];
        #pragma unroll
        for (int j = 0; j < 4; j++) mk[j] = ms[k0 + tx * 4 + j];
        #pragma unroll
        for (int i = 0; i < 4; i++) {
            #pragma unroll
            for (int j = 0; j < 4; j++) {
                float v = s[i][j] * mk[j];
                s[i][j] = (v == 0.0f) ? -INFINITY : v;
            }
            float m2 = fmaxf(fmaxf(s[i][0], s[i][1]), fmaxf(s[i][2], s[i][3]));
            #pragma unroll
            for (int off = 8; off; off >>= 1)
                m2 = fmaxf(m2, __shfl_xor_sync(0xffffffffu, m2, off, 16));
            float mnew = fmaxf(m_run[i], m2);
            float corr = __expf(m_run[i] - mnew);
            float ts = 0.f;
            #pragma unroll
            for (int j = 0; j < 4; j++) {
                float p = __expf(s[i][j] - mnew);
                s[i][j] = p;
                ts += p;
            }
            #pragma unroll
            for (int off = 8; off; off >>= 1)
                ts += __shfl_xor_sync(0xffffffffu, ts, off, 16);
            l_run[i] = l_run[i] * corr + ts;
            m_run[i] = mnew;
            #pragma unroll
            for (int j = 0; j < 4; j++) o[i][j] *= corr;
        }
        __syncthreads();   // all warps done reading Ks before Ps overwrite

        #pragma unroll
        for (int i = 0; i < 4; i++)
            *(float4*)&Ps[ty * 4 + i][tx * 4] =
                make_float4(s[i][0], s[i][1], s[i][2], s[i][3]);
        __syncthreads();

        // P @ V
        #pragma unroll 4
        for (int kk4 = 0; kk4 < 64; kk4 += 4) {
            float4 a4[4];
            #pragma unroll
            for (int i = 0; i < 4; i++) a4[i] = *(const float4*)&Ps[ty * 4 + i][kk4];
            #pragma unroll
            for (int m = 0; m < 4; m++) {
                float4 bv = *(const float4*)&Vs[kk4 + m][tx * 4];
                #pragma unroll
                for (int i = 0; i < 4; i++) {
                    float av = ((const float*)&a4[i])[m];
                    o[i][0] = fmaf(av, bv.x, o[i][0]);
                    o[i][1] = fmaf(av, bv.y, o[i][1]);
                    o[i][2] = fmaf(av, bv.z, o[i][2]);
                    o[i][3] = fmaf(av, bv.w, o[i][3]);
                }
            }
        }
    }

    // finalize
    #pragma unroll
    for (int i = 0; i < 4; i++) {
        float inv = 1.0f / l_run[i];
        int q = q0 + ty * 4 + i;
        float4 o4 = make_float4(o[i][0] * inv, o[i][1] * inv, o[i][2] * inv, o[i][3] * inv);
        *(float4*)&out[((size_t)(b * 512 + q)) * 1024 + h * 64 + tx * 4] = o4;
    }
}

// ---------------------------------------------------------------------------
static const int FLASH_SMEM = (8192 + 8192 + 64 * 68 + 512) * 4;  // 84992 B

extern "C" void kernel_launch(void* const* d_in, const int* in_sizes, int n_in,
                              void* d_out, int out_size) {
    const float* x    = (const float*)d_in[0];  // (8,512,1024)
    const float* mask = (const float*)d_in[1];  // (8,512)
    const float* W    = (const float*)d_in[2];  // (1024,2048)
    const float* rr   = (const float*)d_in[3];  // r_r_bias (16,64)
    const float* rw   = (const float*)d_in[4];  // r_w_bias (16,64)
    float* out = (float*)d_out;                 // (8,512,1024)

    cudaFuncSetAttribute(flash_attn, cudaFuncAttributeMaxDynamicSharedMemorySize,
                         FLASH_SMEM);

    rot_kernel<<<512, 64>>>();
    qv_gemm_tf32<<<dim3(16, 32), 256>>>(x, W);
    qe_build<<<dim3(128, 128), 256>>>(rr, rw);
    flash_attn<<<dim3(8, 128), 256, FLASH_SMEM>>>(x, mask, out);
}

// round 4
// speedup vs baseline: 2.5784x; 1.4469x over previous
#include <cuda_runtime.h>
#include <cuda_fp16.h>
#include <math.h>
#include <stdint.h>

#define BB 8
#define LL 512
#define DM 1024
#define NH 16
#define HD 64
#define BH (BB*NH)     // 128

// ---- scratch (device globals; allocation-free rule) ----
__device__ float  g_q  [(size_t)BH*LL*HD];      // 16 MB  (bh,l,d) fp32
__device__ float  g_v  [(size_t)BH*LL*HD];      // 16 MB
__device__ float  g_rot[(size_t)LL*64];         // 128 KB
__device__ __half g_xh [(size_t)4096*1024];     // 8 MB  x split hi  [m][k]
__device__ __half g_xl [(size_t)4096*1024];     // 8 MB
__device__ __half g_wth[(size_t)2048*1024];     // 4 MB  W^T split hi [n][k]
__device__ __half g_wtl[(size_t)2048*1024];     // 4 MB
__device__ __half g_qeh[(size_t)BH*LL*128];     // 16 MB  Qe hi [bh][q][c]
__device__ __half g_qel[(size_t)BH*LL*128];     // 16 MB
__device__ __half g_keh[(size_t)BH*LL*128];     // 16 MB  Ke hi [bh][k][c]
__device__ __half g_kel[(size_t)BH*LL*128];     // 16 MB
__device__ __half g_vth[(size_t)BH*HD*LL];      // 8 MB   V^T hi [bh][d][k]
__device__ __half g_vtl[(size_t)BH*HD*LL];      // 8 MB

// ---------------------------------------------------------------------------
__device__ __forceinline__ uint32_t pack2h(__half a, __half b) {
    __half2 p = __halves2half2(a, b);
    return *reinterpret_cast<uint32_t*>(&p);
}

__device__ __forceinline__ void split4(float4 v, uint2& hi, uint2& lo) {
    __half h0 = __float2half_rn(v.x), h1 = __float2half_rn(v.y);
    __half h2 = __float2half_rn(v.z), h3 = __float2half_rn(v.w);
    hi.x = pack2h(h0, h1); hi.y = pack2h(h2, h3);
    lo.x = pack2h(__float2half_rn(v.x - __half2float(h0)),
                  __float2half_rn(v.y - __half2float(h1)));
    lo.y = pack2h(__float2half_rn(v.z - __half2float(h2)),
                  __float2half_rn(v.w - __half2float(h3)));
}

__device__ __forceinline__ void mma_f16(float* c, const uint32_t* a, const uint32_t* b) {
    asm volatile(
        "mma.sync.aligned.m16n8k16.row.col.f32.f16.f16.f32 "
        "{%0,%1,%2,%3}, {%4,%5,%6,%7}, {%8,%9}, {%0,%1,%2,%3};\n"
        : "+f"(c[0]), "+f"(c[1]), "+f"(c[2]), "+f"(c[3])
        : "r"(a[0]), "r"(a[1]), "r"(a[2]), "r"(a[3]), "r"(b[0]), "r"(b[1]));
}

// ---------------------------------------------------------------------------
// rot table
// ---------------------------------------------------------------------------
__global__ void rot_kernel() {
    int k = blockIdx.x, d = threadIdx.x;
    int i = d & 31;
    float w = expf(-(float)i * (logf(10000.0f) / 31.0f));
    float ang = (float)k * w;
    g_rot[k * 64 + d] = (d < 32) ? sinf(ang) : cosf(ang);
}

// ---------------------------------------------------------------------------
// prep_x: x fp32 -> split halves [m][k]
// ---------------------------------------------------------------------------
__global__ __launch_bounds__(256) void prep_x(const float* __restrict__ X) {
    int idx = blockIdx.x * 256 + threadIdx.x;  // float4 units, total 1048576
    float4 v = ((const float4*)X)[idx];
    uint2 hi, lo; split4(v, hi, lo);
    ((uint2*)g_xh)[idx] = hi;
    ((uint2*)g_xl)[idx] = lo;
}

// ---------------------------------------------------------------------------
// prep_w: W [k][n] fp32 -> W^T split halves [n][k]
// ---------------------------------------------------------------------------
__global__ __launch_bounds__(256) void prep_w(const float* __restrict__ W) {
    __shared__ float tile[32][33];
    int n0 = blockIdx.x * 32, k0 = blockIdx.y * 32;
    int t = threadIdx.x;
    int row = t >> 3, c4 = (t & 7) * 4;
    float4 v = *(const float4*)&W[(size_t)(k0 + row) * 2048 + n0 + c4];
    tile[row][c4 + 0] = v.x; tile[row][c4 + 1] = v.y;
    tile[row][c4 + 2] = v.z; tile[row][c4 + 3] = v.w;
    __syncthreads();
    float4 o = make_float4(tile[c4 + 0][row], tile[c4 + 1][row],
                           tile[c4 + 2][row], tile[c4 + 3][row]);
    uint2 hi, lo; split4(o, hi, lo);
    *(uint2*)&g_wth[(size_t)(n0 + row) * 1024 + k0 + c4] = hi;
    *(uint2*)&g_wtl[(size_t)(n0 + row) * 1024 + k0 + c4] = lo;
}

// ---------------------------------------------------------------------------
// qv GEMM, fp16-split mma: C = X @ W, M=4096, N=2048, K=1024
// 128x128 tile, BK=32, 8 warps (4x2), warp 32x64, m16n8k16.
// ---------------------------------------------------------------------------
__global__ __launch_bounds__(256) void qv_gemm_f16() {
    __shared__ __half Ah[128][40], Al[128][40];   // [m][k] pad 8
    __shared__ __half Bh[128][40], Bl[128][40];   // [n][k] pad 8
    int t = threadIdx.x, lane = t & 31, warp = t >> 5;
    int m0 = blockIdx.y * 128, n0 = blockIdx.x * 128;
    int wm = (warp >> 1) * 32, wn = (warp & 1) * 64;
    int r = lane >> 2, c2 = (lane & 3) * 2;

    float acc[2][8][4];
    #pragma unroll
    for (int mt = 0; mt < 2; mt++)
        #pragma unroll
        for (int nt = 0; nt < 8; nt++)
            #pragma unroll
            for (int j = 0; j < 4; j++) acc[mt][nt][j] = 0.f;

    for (int k0 = 0; k0 < 1024; k0 += 32) {
        #pragma unroll
        for (int i = 0; i < 2; i++) {
            int idx = t + 256 * i;
            int row = idx >> 2, seg = (idx & 3) * 8;
            size_t ga = (size_t)(m0 + row) * 1024 + k0 + seg;
            size_t gb = (size_t)(n0 + row) * 1024 + k0 + seg;
            *(uint4*)&Ah[row][seg] = *(const uint4*)&g_xh[ga];
            *(uint4*)&Al[row][seg] = *(const uint4*)&g_xl[ga];
            *(uint4*)&Bh[row][seg] = *(const uint4*)&g_wth[gb];
            *(uint4*)&Bl[row][seg] = *(const uint4*)&g_wtl[gb];
        }
        __syncthreads();

        #pragma unroll
        for (int s = 0; s < 2; s++) {
            uint32_t ah[2][4], al[2][4];
            #pragma unroll
            for (int mt = 0; mt < 2; mt++) {
                int rr = wm + mt * 16 + r;
                ah[mt][0] = *(const uint32_t*)&Ah[rr][s * 16 + c2];
                ah[mt][1] = *(const uint32_t*)&Ah[rr + 8][s * 16 + c2];
                ah[mt][2] = *(const uint32_t*)&Ah[rr][s * 16 + 8 + c2];
                ah[mt][3] = *(const uint32_t*)&Ah[rr + 8][s * 16 + 8 + c2];
                al[mt][0] = *(const uint32_t*)&Al[rr][s * 16 + c2];
                al[mt][1] = *(const uint32_t*)&Al[rr + 8][s * 16 + c2];
                al[mt][2] = *(const uint32_t*)&Al[rr][s * 16 + 8 + c2];
                al[mt][3] = *(const uint32_t*)&Al[rr + 8][s * 16 + 8 + c2];
            }
            #pragma unroll
            for (int nt = 0; nt < 8; nt++) {
                int nn = wn + nt * 8 + r;
                uint32_t bhf[2], blf[2];
                bhf[0] = *(const uint32_t*)&Bh[nn][s * 16 + c2];
                bhf[1] = *(const uint32_t*)&Bh[nn][s * 16 + 8 + c2];
                blf[0] = *(const uint32_t*)&Bl[nn][s * 16 + c2];
                blf[1] = *(const uint32_t*)&Bl[nn][s * 16 + 8 + c2];
                mma_f16(acc[0][nt], ah[0], bhf);
                mma_f16(acc[1][nt], ah[1], bhf);
                mma_f16(acc[0][nt], ah[0], blf);
                mma_f16(acc[1][nt], ah[1], blf);
                mma_f16(acc[0][nt], al[0], bhf);
                mma_f16(acc[1][nt], al[1], bhf);
            }
        }
        __syncthreads();
    }

    // epilogue: scatter into g_q / g_v
    #pragma unroll
    for (int mt = 0; mt < 2; mt++) {
        #pragma unroll
        for (int nt = 0; nt < 8; nt++) {
            int r0 = m0 + wm + mt * 16 + r;
            int cc = n0 + wn + nt * 8 + c2;
            #pragma unroll
            for (int half_ = 0; half_ < 2; half_++) {
                int m = r0 + half_ * 8;
                float2 val = make_float2(acc[mt][nt][half_ * 2],
                                         acc[mt][nt][half_ * 2 + 1]);
                int bi = m >> 9, l = m & 511;
                if (cc < 1024) {
                    int h = cc >> 6, d = cc & 63;
                    *(float2*)&g_q[(((size_t)(bi * 16 + h) * 512) + l) * 64 + d] = val;
                } else {
                    int n2 = cc - 1024;
                    int h = n2 >> 6, d = n2 & 63;
                    *(float2*)&g_v[(((size_t)(bi * 16 + h) * 512) + l) * 64 + d] = val;
                }
            }
        }
    }
}

// ---------------------------------------------------------------------------
// qe_build: Qe[0:64]=q+rr ; Qe[64:128]=rot_q(q+rw); split to halves
// ---------------------------------------------------------------------------
__global__ __launch_bounds__(256) void qe_build(const float* __restrict__ rr,
                                                const float* __restrict__ rw) {
    __shared__ float u[4][64];
    int bh = blockIdx.x, h = bh & 15;
    int row = threadIdx.x >> 6;
    int d = threadIdx.x & 63;
    int q = blockIdx.y * 4 + row;

    float qv = g_q[((size_t)bh * 512 + q) * 64 + d];
    float outA = qv + rr[h * 64 + d];
    float uu = qv + rw[h * 64 + d];
    u[row][d] = uu;
    __syncthreads();
    int i = d & 31;
    float sq = g_rot[q * 64 + i];
    float cq = g_rot[q * 64 + 32 + i];
    float partner = u[row][d ^ 32];
    float outB = uu * cq + ((d < 32) ? partner : -partner) * sq;

    size_t base = ((size_t)bh * 512 + q) * 128;
    __half ha = __float2half_rn(outA);
    __half hb = __float2half_rn(outB);
    g_qeh[base + d] = ha;
    g_qeh[base + 64 + d] = hb;
    g_qel[base + d] = __float2half_rn(outA - __half2float(ha));
    g_qel[base + 64 + d] = __float2half_rn(outB - __half2float(hb));
}

// ---------------------------------------------------------------------------
// ke_build: Ke[k][c<64]=x[b,k,h*64+c]; Ke[k][64+j]=rot[k][j]; split halves
// ---------------------------------------------------------------------------
__global__ __launch_bounds__(256) void ke_build(const float* __restrict__ X) {
    int bh = blockIdx.x;
    int b = bh >> 4, h = bh & 15;
    int kbase = blockIdx.y * 64;
    for (int i = threadIdx.x; i < 64 * 128; i += 256) {
        int k = kbase + (i >> 7), c = i & 127;
        float f = (c < 64) ? X[((size_t)(b * 512) + k) * 1024 + h * 64 + c]
                           : g_rot[k * 64 + (c - 64)];
        __half hi = __float2half_rn(f);
        size_t o = ((size_t)bh * 512 + k) * 128 + c;
        g_keh[o] = hi;
        g_kel[o] = __float2half_rn(f - __half2float(hi));
    }
}

// ---------------------------------------------------------------------------
// build_vt: g_v [bh][k][d] fp32 -> split halves transposed [bh][d][k]
// ---------------------------------------------------------------------------
__global__ __launch_bounds__(256) void build_vt() {
    __shared__ float tile[64][65];
    int bh = blockIdx.x;
    int k0 = blockIdx.y * 64;
    int t = threadIdx.x;
    #pragma unroll
    for (int i = 0; i < 4; i++) {
        int idx = t + 256 * i;
        int kk = idx >> 4, d4 = (idx & 15) * 4;
        float4 v = *(const float4*)&g_v[((size_t)bh * 512 + k0 + kk) * 64 + d4];
        tile[kk][d4 + 0] = v.x; tile[kk][d4 + 1] = v.y;
        tile[kk][d4 + 2] = v.z; tile[kk][d4 + 3] = v.w;
    }
    __syncthreads();
    #pragma unroll
    for (int i = 0; i < 4; i++) {
        int idx = t + 256 * i;
        int d = idx >> 4, kk4 = (idx & 15) * 4;
        float4 o = make_float4(tile[kk4 + 0][d], tile[kk4 + 1][d],
                               tile[kk4 + 2][d], tile[kk4 + 3][d]);
        uint2 hi, lo; split4(o, hi, lo);
        *(uint2*)&g_vth[((size_t)bh * 64 + d) * 512 + k0 + kk4] = hi;
        *(uint2*)&g_vtl[((size_t)bh * 64 + d) * 512 + k0 + kk4] = lo;
    }
}

// ---------------------------------------------------------------------------
// Flash attention, fp16-split mma. Block = (b,h) x q-tile 64, 128 threads.
// S = Qe(64x128) . Ke^T(64x128) -> online softmax -> O += P.V
// smem halves: Qh/Ql [64][136], Kh/Kl [64][136], Vh/Vl [64][72], ms f32[512]
// ---------------------------------------------------------------------------
#define QK_STR 136
#define V_STR  72
#define OFF_QL (64*QK_STR)
#define OFF_KH (2*64*QK_STR)
#define OFF_KL (3*64*QK_STR)
#define OFF_VH (4*64*QK_STR)
#define OFF_VL (4*64*QK_STR + 64*V_STR)
#define OFF_END (4*64*QK_STR + 2*64*V_STR)
#define FLASH_SMEM (OFF_END*2 + 512*4)

__global__ __launch_bounds__(128) void flash_attn(const float* __restrict__ mask,
                                                  float* __restrict__ out) {
    extern __shared__ __half sh[];
    __half* Qh = sh;
    __half* Ql = sh + OFF_QL;
    __half* Kh = sh + OFF_KH;
    __half* Kl = sh + OFF_KL;
    __half* Vh = sh + OFF_VH;
    __half* Vl = sh + OFF_VL;
    float*  ms = (float*)(sh + OFF_END);

    int qt = blockIdx.x, bh = blockIdx.y;
    int b = bh >> 4, h = bh & 15;
    int q0 = qt * 64;
    int t = threadIdx.x, lane = t & 31, warp = t >> 5;
    int r = lane >> 2, c2 = (lane & 3) * 2;
    int wq = warp * 16;

    #pragma unroll
    for (int i = 0; i < 4; i++) ms[t + 128 * i] = mask[b * 512 + t + 128 * i];

    #pragma unroll
    for (int i = 0; i < 8; i++) {
        int idx = t + 128 * i;
        int q = idx >> 4, u = (idx & 15) * 8;
        size_t g = ((size_t)bh * 512 + q0 + q) * 128 + u;
        *(uint4*)&Qh[q * QK_STR + u] = *(const uint4*)&g_qeh[g];
        *(uint4*)&Ql[q * QK_STR + u] = *(const uint4*)&g_qel[g];
    }

    float m_run[2] = {-1e30f, -1e30f}, l_run[2] = {0.f, 0.f};
    float o[8][4];
    #pragma unroll
    for (int nt = 0; nt < 8; nt++)
        #pragma unroll
        for (int j = 0; j < 4; j++) o[nt][j] = 0.f;

    for (int k0 = 0; k0 < 512; k0 += 64) {
        __syncthreads();
        #pragma unroll
        for (int i = 0; i < 8; i++) {
            int idx = t + 128 * i;
            int k = idx >> 4, u = (idx & 15) * 8;
            size_t g = ((size_t)bh * 512 + k0 + k) * 128 + u;
            *(uint4*)&Kh[k * QK_STR + u] = *(const uint4*)&g_keh[g];
            *(uint4*)&Kl[k * QK_STR + u] = *(const uint4*)&g_kel[g];
        }
        #pragma unroll
        for (int i = 0; i < 4; i++) {
            int idx = t + 128 * i;
            int d = idx >> 3, u = (idx & 7) * 8;
            size_t g = ((size_t)bh * 64 + d) * 512 + k0 + u;
            *(uint4*)&Vh[d * V_STR + u] = *(const uint4*)&g_vth[g];
            *(uint4*)&Vl[d * V_STR + u] = *(const uint4*)&g_vtl[g];
        }
        __syncthreads();

        // ---- S = Qe . Ke^T (K-dim 128, 8 k16 steps) ----
        float s[8][4];
        #pragma unroll
        for (int nt = 0; nt < 8; nt++)
            #pragma unroll
            for (int j = 0; j < 4; j++) s[nt][j] = 0.f;

        #pragma unroll
        for (int st = 0; st < 8; st++) {
            int qq = wq + r;
            uint32_t ah[4], al[4];
            ah[0] = *(const uint32_t*)&Qh[qq * QK_STR + st * 16 + c2];
            ah[1] = *(const uint32_t*)&Qh[(qq + 8) * QK_STR + st * 16 + c2];
            ah[2] = *(const uint32_t*)&Qh[qq * QK_STR + st * 16 + 8 + c2];
            ah[3] = *(const uint32_t*)&Qh[(qq + 8) * QK_STR + st * 16 + 8 + c2];
            al[0] = *(const uint32_t*)&Ql[qq * QK_STR + st * 16 + c2];
            al[1] = *(const uint32_t*)&Ql[(qq + 8) * QK_STR + st * 16 + c2];
            al[2] = *(const uint32_t*)&Ql[qq * QK_STR + st * 16 + 8 + c2];
            al[3] = *(const uint32_t*)&Ql[(qq + 8) * QK_STR + st * 16 + 8 + c2];
            #pragma unroll
            for (int nt = 0; nt < 8; nt++) {
                int nn = nt * 8 + r;
                uint32_t bhf[2], blf[2];
                bhf[0] = *(const uint32_t*)&Kh[nn * QK_STR + st * 16 + c2];
                bhf[1] = *(const uint32_t*)&Kh[nn * QK_STR + st * 16 + 8 + c2];
                blf[0] = *(const uint32_t*)&Kl[nn * QK_STR + st * 16 + c2];
                blf[1] = *(const uint32_t*)&Kl[nn * QK_STR + st * 16 + 8 + c2];
                mma_f16(s[nt], ah, bhf);
                mma_f16(s[nt], ah, blf);
                mma_f16(s[nt], al, bhf);
            }
        }

        // ---- mask + online softmax ----
        float mnew0 = m_run[0], mnew1 = m_run[1];
        #pragma unroll
        for (int nt = 0; nt < 8; nt++) {
            int kc = k0 + nt * 8 + c2;
            float mk0 = ms[kc], mk1 = ms[kc + 1];
            float v0 = s[nt][0] * mk0; s[nt][0] = (v0 == 0.f) ? -INFINITY : v0;
            float v1 = s[nt][1] * mk1; s[nt][1] = (v1 == 0.f) ? -INFINITY : v1;
            float v2 = s[nt][2] * mk0; s[nt][2] = (v2 == 0.f) ? -INFINITY : v2;
            float v3 = s[nt][3] * mk1; s[nt][3] = (v3 == 0.f) ? -INFINITY : v3;
            mnew0 = fmaxf(mnew0, fmaxf(s[nt][0], s[nt][1]));
            mnew1 = fmaxf(mnew1, fmaxf(s[nt][2], s[nt][3]));
        }
        #pragma unroll
        for (int off = 1; off <= 2; off <<= 1) {
            mnew0 = fmaxf(mnew0, __shfl_xor_sync(0xffffffffu, mnew0, off));
            mnew1 = fmaxf(mnew1, __shfl_xor_sync(0xffffffffu, mnew1, off));
        }
        float corr0 = __expf(m_run[0] - mnew0);
        float corr1 = __expf(m_run[1] - mnew1);
        float ts0 = 0.f, ts1 = 0.f;
        #pragma unroll
        for (int nt = 0; nt < 8; nt++) {
            float p0 = __expf(s[nt][0] - mnew0); s[nt][0] = p0;
            float p1 = __expf(s[nt][1] - mnew0); s[nt][1] = p1;
            float p2 = __expf(s[nt][2] - mnew1); s[nt][2] = p2;
            float p3 = __expf(s[nt][3] - mnew1); s[nt][3] = p3;
            ts0 += p0 + p1; ts1 += p2 + p3;
        }
        #pragma unroll
        for (int off = 1; off <= 2; off <<= 1) {
            ts0 += __shfl_xor_sync(0xffffffffu, ts0, off);
            ts1 += __shfl_xor_sync(0xffffffffu, ts1, off);
        }
        l_run[0] = l_run[0] * corr0 + ts0;
        l_run[1] = l_run[1] * corr1 + ts1;
        m_run[0] = mnew0; m_run[1] = mnew1;
        #pragma unroll
        for (int nt = 0; nt < 8; nt++) {
            o[nt][0] *= corr0; o[nt][1] *= corr0;
            o[nt][2] *= corr1; o[nt][3] *= corr1;
        }

        // ---- O += P . V (kseq 64 = 4 k16 steps; P stays in registers) ----
        #pragma unroll
        for (int s2 = 0; s2 < 4; s2++) {
            float* pa = s[2 * s2];
            float* pb = s[2 * s2 + 1];
            __half h00 = __float2half_rn(pa[0]), h01 = __float2half_rn(pa[1]);
            __half h02 = __float2half_rn(pa[2]), h03 = __float2half_rn(pa[3]);
            __half h10 = __float2half_rn(pb[0]), h11 = __float2half_rn(pb[1]);
            __half h12 = __float2half_rn(pb[2]), h13 = __float2half_rn(pb[3]);
            uint32_t ph[4], pl[4];
            ph[0] = pack2h(h00, h01);
            ph[1] = pack2h(h02, h03);
            ph[2] = pack2h(h10, h11);
            ph[3] = pack2h(h12, h13);
            pl[0] = pack2h(__float2half_rn(pa[0] - __half2float(h00)),
                           __float2half_rn(pa[1] - __half2float(h01)));
            pl[1] = pack2h(__float2half_rn(pa[2] - __half2float(h02)),
                           __float2half_rn(pa[3] - __half2float(h03)));
            pl[2] = pack2h(__float2half_rn(pb[0] - __half2float(h10)),
                           __float2half_rn(pb[1] - __half2float(h11)));
            pl[3] = pack2h(__float2half_rn(pb[2] - __half2float(h12)),
                           __float2half_rn(pb[3] - __half2float(h13)));
            #pragma unroll
            for (int ntd = 0; ntd < 8; ntd++) {
                int dd = ntd * 8 + r;
                uint32_t bhf[2], blf[2];
                bhf[0] = *(const uint32_t*)&Vh[dd * V_STR + s2 * 16 + c2];
                bhf[1] = *(const uint32_t*)&Vh[dd * V_STR + s2 * 16 + 8 + c2];
                blf[0] = *(const uint32_t*)&Vl[dd * V_STR + s2 * 16 + c2];
                blf[1] = *(const uint32_t*)&Vl[dd * V_STR + s2 * 16 + 8 + c2];
                mma_f16(o[ntd], ph, bhf);
                mma_f16(o[ntd], ph, blf);
                mma_f16(o[ntd], pl, bhf);
            }
        }
    }

    // ---- finalize ----
    float inv0 = 1.0f / l_run[0], inv1 = 1.0f / l_run[1];
    int qg0 = q0 + wq + r;
    #pragma unroll
    for (int ntd = 0; ntd < 8; ntd++) {
        int d = ntd * 8 + c2;
        *(float2*)&out[((size_t)(b * 512) + qg0) * 1024 + h * 64 + d] =
            make_float2(o[ntd][0] * inv0, o[ntd][1] * inv0);
        *(float2*)&out[((size_t)(b * 512) + qg0 + 8) * 1024 + h * 64 + d] =
            make_float2(o[ntd][2] * inv1, o[ntd][3] * inv1);
    }
}

// ---------------------------------------------------------------------------
extern "C" void kernel_launch(void* const* d_in, const int* in_sizes, int n_in,
                              void* d_out, int out_size) {
    const float* x    = (const float*)d_in[0];
    const float* mask = (const float*)d_in[1];
    const float* W    = (const float*)d_in[2];
    const float* rr   = (const float*)d_in[3];
    const float* rw   = (const float*)d_in[4];
    float* out = (float*)d_out;

    cudaFuncSetAttribute(flash_attn, cudaFuncAttributeMaxDynamicSharedMemorySize,
                         FLASH_SMEM);

    rot_kernel<<<512, 64>>>();
    prep_x<<<4096, 256>>>(x);
    prep_w<<<dim3(64, 32), 256>>>(W);
    qv_gemm_f16<<<dim3(16, 32), 256>>>();
    qe_build<<<dim3(128, 128), 256>>>(rr, rw);
    ke_build<<<dim3(128, 8), 256>>>(x);
    build_vt<<<dim3(128, 8), 256>>>();
    flash_attn<<<dim3(8, 128), 128, FLASH_SMEM>>>(mask, out);
}

// round 5
// speedup vs baseline: 2.7021x; 1.0480x over previous
#include <cuda_runtime.h>
#include <cuda_fp16.h>
#include <math.h>
#include <stdint.h>

#define BB 8
#define LL 512
#define DM 1024
#define NH 16
#define HD 64
#define BH (BB*NH)     // 128

// ---- scratch (device globals; allocation-free rule) ----
__device__ float  g_q  [(size_t)BH*LL*HD];
__device__ float  g_v  [(size_t)BH*LL*HD];
__device__ float  g_rot[(size_t)LL*64];
__device__ __align__(16) __half g_xh [(size_t)4096*1024];
__device__ __align__(16) __half g_xl [(size_t)4096*1024];
__device__ __align__(16) __half g_wth[(size_t)2048*1024];
__device__ __align__(16) __half g_wtl[(size_t)2048*1024];
__device__ __align__(16) __half g_qeh[(size_t)BH*LL*128];
__device__ __align__(16) __half g_qel[(size_t)BH*LL*128];
__device__ __align__(16) __half g_keh[(size_t)BH*LL*128];
__device__ __align__(16) __half g_kel[(size_t)BH*LL*128];
__device__ __align__(16) __half g_vth[(size_t)BH*HD*LL];
__device__ __align__(16) __half g_vtl[(size_t)BH*HD*LL];

// ---------------------------------------------------------------------------
__device__ __forceinline__ uint32_t pack2h(__half a, __half b) {
    __half2 p = __halves2half2(a, b);
    return *reinterpret_cast<uint32_t*>(&p);
}
__device__ __forceinline__ void split4(float4 v, uint2& hi, uint2& lo) {
    __half h0 = __float2half_rn(v.x), h1 = __float2half_rn(v.y);
    __half h2 = __float2half_rn(v.z), h3 = __float2half_rn(v.w);
    hi.x = pack2h(h0, h1); hi.y = pack2h(h2, h3);
    lo.x = pack2h(__float2half_rn(v.x - __half2float(h0)),
                  __float2half_rn(v.y - __half2float(h1)));
    lo.y = pack2h(__float2half_rn(v.z - __half2float(h2)),
                  __float2half_rn(v.w - __half2float(h3)));
}
__device__ __forceinline__ void mma_f16(float* c, const uint32_t* a, const uint32_t* b) {
    asm volatile(
        "mma.sync.aligned.m16n8k16.row.col.f32.f16.f16.f32 "
        "{%0,%1,%2,%3}, {%4,%5,%6,%7}, {%8,%9}, {%0,%1,%2,%3};\n"
        : "+f"(c[0]), "+f"(c[1]), "+f"(c[2]), "+f"(c[3])
        : "r"(a[0]), "r"(a[1]), "r"(a[2]), "r"(a[3]), "r"(b[0]), "r"(b[1]));
}
__device__ __forceinline__ void cp16(void* dst, const void* src) {
    uint32_t s = (uint32_t)__cvta_generic_to_shared(dst);
    asm volatile("cp.async.cg.shared.global [%0], [%1], 16;\n" :: "r"(s), "l"(src));
}
#define CP_COMMIT asm volatile("cp.async.commit_group;\n")
#define CP_WAIT1  asm volatile("cp.async.wait_group 1;\n")
#define CP_WAIT0  asm volatile("cp.async.wait_group 0;\n")

// ---------------------------------------------------------------------------
__global__ void rot_kernel() {
    int k = blockIdx.x, d = threadIdx.x;
    int i = d & 31;
    float w = expf(-(float)i * (logf(10000.0f) / 31.0f));
    float ang = (float)k * w;
    g_rot[k * 64 + d] = (d < 32) ? sinf(ang) : cosf(ang);
}

__global__ __launch_bounds__(256) void prep_x(const float* __restrict__ X) {
    int idx = blockIdx.x * 256 + threadIdx.x;
    float4 v = ((const float4*)X)[idx];
    uint2 hi, lo; split4(v, hi, lo);
    ((uint2*)g_xh)[idx] = hi;
    ((uint2*)g_xl)[idx] = lo;
}

__global__ __launch_bounds__(256) void prep_w(const float* __restrict__ W) {
    __shared__ float tile[32][33];
    int n0 = blockIdx.x * 32, k0 = blockIdx.y * 32;
    int t = threadIdx.x;
    int row = t >> 3, c4 = (t & 7) * 4;
    float4 v = *(const float4*)&W[(size_t)(k0 + row) * 2048 + n0 + c4];
    tile[row][c4 + 0] = v.x; tile[row][c4 + 1] = v.y;
    tile[row][c4 + 2] = v.z; tile[row][c4 + 3] = v.w;
    __syncthreads();
    float4 o = make_float4(tile[c4 + 0][row], tile[c4 + 1][row],
                           tile[c4 + 2][row], tile[c4 + 3][row]);
    uint2 hi, lo; split4(o, hi, lo);
    *(uint2*)&g_wth[(size_t)(n0 + row) * 1024 + k0 + c4] = hi;
    *(uint2*)&g_wtl[(size_t)(n0 + row) * 1024 + k0 + c4] = lo;
}

// ---------------------------------------------------------------------------
// qv GEMM with 2-stage cp.async pipeline. C = X @ W, M=4096, N=2048, K=1024.
// 128x128 tile, BK=32, 8 warps (4x2), warp 32x64, m16n8k16, 3-mma split.
// ---------------------------------------------------------------------------
#define QV_PS (128*40)        // halves per buffer
#define QV_SS (4*QV_PS)       // halves per stage (Ah,Al,Bh,Bl)
#define QV_SMEM (2*QV_SS*2)   // bytes = 81920

__device__ __forceinline__ void qv_issue(__half* qsm, int stage, int k0,
                                         int m0, int n0, int t) {
    __half* base = qsm + stage * QV_SS;
    #pragma unroll
    for (int i = 0; i < 2; i++) {
        int c = t + 256 * i;
        int row = c >> 2, seg = (c & 3) * 8;
        size_t ga = (size_t)(m0 + row) * 1024 + k0 + seg;
        size_t gb = (size_t)(n0 + row) * 1024 + k0 + seg;
        cp16(base + row * 40 + seg,               g_xh  + ga);
        cp16(base + QV_PS + row * 40 + seg,       g_xl  + ga);
        cp16(base + 2 * QV_PS + row * 40 + seg,   g_wth + gb);
        cp16(base + 3 * QV_PS + row * 40 + seg,   g_wtl + gb);
    }
}

__global__ __launch_bounds__(256) void qv_gemm_f16() {
    extern __shared__ __half qsm[];
    int t = threadIdx.x, lane = t & 31, warp = t >> 5;
    int m0 = blockIdx.y * 128, n0 = blockIdx.x * 128;
    int wm = (warp >> 1) * 32, wn = (warp & 1) * 64;
    int r = lane >> 2, c2 = (lane & 3) * 2;

    float acc[2][8][4];
    #pragma unroll
    for (int mt = 0; mt < 2; mt++)
        #pragma unroll
        for (int nt = 0; nt < 8; nt++)
            #pragma unroll
            for (int j = 0; j < 4; j++) acc[mt][nt][j] = 0.f;

    qv_issue(qsm, 0, 0, m0, n0, t);
    CP_COMMIT;

    for (int it = 0; it < 32; it++) {
        if (it < 31) {
            qv_issue(qsm, (it + 1) & 1, (it + 1) * 32, m0, n0, t);
            CP_COMMIT;
            CP_WAIT1;
        } else {
            CP_WAIT0;
        }
        __syncthreads();

        const __half* Ah = qsm + (it & 1) * QV_SS;
        const __half* Al = Ah + QV_PS;
        const __half* Bh = Ah + 2 * QV_PS;
        const __half* Bl = Ah + 3 * QV_PS;

        #pragma unroll
        for (int s = 0; s < 2; s++) {
            uint32_t ah[2][4], al[2][4];
            #pragma unroll
            for (int mt = 0; mt < 2; mt++) {
                int rr = wm + mt * 16 + r;
                ah[mt][0] = *(const uint32_t*)&Ah[rr * 40 + s * 16 + c2];
                ah[mt][1] = *(const uint32_t*)&Ah[(rr + 8) * 40 + s * 16 + c2];
                ah[mt][2] = *(const uint32_t*)&Ah[rr * 40 + s * 16 + 8 + c2];
                ah[mt][3] = *(const uint32_t*)&Ah[(rr + 8) * 40 + s * 16 + 8 + c2];
                al[mt][0] = *(const uint32_t*)&Al[rr * 40 + s * 16 + c2];
                al[mt][1] = *(const uint32_t*)&Al[(rr + 8) * 40 + s * 16 + c2];
                al[mt][2] = *(const uint32_t*)&Al[rr * 40 + s * 16 + 8 + c2];
                al[mt][3] = *(const uint32_t*)&Al[(rr + 8) * 40 + s * 16 + 8 + c2];
            }
            #pragma unroll
            for (int nt = 0; nt < 8; nt++) {
                int nn = wn + nt * 8 + r;
                uint32_t bhf[2], blf[2];
                bhf[0] = *(const uint32_t*)&Bh[nn * 40 + s * 16 + c2];
                bhf[1] = *(const uint32_t*)&Bh[nn * 40 + s * 16 + 8 + c2];
                blf[0] = *(const uint32_t*)&Bl[nn * 40 + s * 16 + c2];
                blf[1] = *(const uint32_t*)&Bl[nn * 40 + s * 16 + 8 + c2];
                mma_f16(acc[0][nt], ah[0], bhf);
                mma_f16(acc[1][nt], ah[1], bhf);
                mma_f16(acc[0][nt], ah[0], blf);
                mma_f16(acc[1][nt], ah[1], blf);
                mma_f16(acc[0][nt], al[0], bhf);
                mma_f16(acc[1][nt], al[1], bhf);
            }
        }
        __syncthreads();
    }

    #pragma unroll
    for (int mt = 0; mt < 2; mt++) {
        #pragma unroll
        for (int nt = 0; nt < 8; nt++) {
            int r0 = m0 + wm + mt * 16 + r;
            int cc = n0 + wn + nt * 8 + c2;
            #pragma unroll
            for (int half_ = 0; half_ < 2; half_++) {
                int m = r0 + half_ * 8;
                float2 val = make_float2(acc[mt][nt][half_ * 2],
                                         acc[mt][nt][half_ * 2 + 1]);
                int bi = m >> 9, l = m & 511;
                if (cc < 1024) {
                    int h = cc >> 6, d = cc & 63;
                    *(float2*)&g_q[(((size_t)(bi * 16 + h) * 512) + l) * 64 + d] = val;
                } else {
                    int n2 = cc - 1024;
                    int h = n2 >> 6, d = n2 & 63;
                    *(float2*)&g_v[(((size_t)(bi * 16 + h) * 512) + l) * 64 + d] = val;
                }
            }
        }
    }
}

// ---------------------------------------------------------------------------
__global__ __launch_bounds__(256) void qe_build(const float* __restrict__ rr,
                                                const float* __restrict__ rw) {
    __shared__ float u[4][64];
    int bh = blockIdx.x, h = bh & 15;
    int row = threadIdx.x >> 6;
    int d = threadIdx.x & 63;
    int q = blockIdx.y * 4 + row;

    float qv = g_q[((size_t)bh * 512 + q) * 64 + d];
    float outA = qv + rr[h * 64 + d];
    float uu = qv + rw[h * 64 + d];
    u[row][d] = uu;
    __syncthreads();
    int i = d & 31;
    float sq = g_rot[q * 64 + i];
    float cq = g_rot[q * 64 + 32 + i];
    float partner = u[row][d ^ 32];
    float outB = uu * cq + ((d < 32) ? partner : -partner) * sq;

    size_t base = ((size_t)bh * 512 + q) * 128;
    __half ha = __float2half_rn(outA);
    __half hb = __float2half_rn(outB);
    g_qeh[base + d] = ha;
    g_qeh[base + 64 + d] = hb;
    g_qel[base + d] = __float2half_rn(outA - __half2float(ha));
    g_qel[base + 64 + d] = __float2half_rn(outB - __half2float(hb));
}

__global__ __launch_bounds__(256) void ke_build(const float* __restrict__ X) {
    int bh = blockIdx.x;
    int b = bh >> 4, h = bh & 15;
    int kbase = blockIdx.y * 64;
    for (int i = threadIdx.x; i < 64 * 128; i += 256) {
        int k = kbase + (i >> 7), c = i & 127;
        float f = (c < 64) ? X[((size_t)(b * 512) + k) * 1024 + h * 64 + c]
                           : g_rot[k * 64 + (c - 64)];
        __half hi = __float2half_rn(f);
        size_t o = ((size_t)bh * 512 + k) * 128 + c;
        g_keh[o] = hi;
        g_kel[o] = __float2half_rn(f - __half2float(hi));
    }
}

__global__ __launch_bounds__(256) void build_vt() {
    __shared__ float tile[64][65];
    int bh = blockIdx.x;
    int k0 = blockIdx.y * 64;
    int t = threadIdx.x;
    #pragma unroll
    for (int i = 0; i < 4; i++) {
        int idx = t + 256 * i;
        int kk = idx >> 4, d4 = (idx & 15) * 4;
        float4 v = *(const float4*)&g_v[((size_t)bh * 512 + k0 + kk) * 64 + d4];
        tile[kk][d4 + 0] = v.x; tile[kk][d4 + 1] = v.y;
        tile[kk][d4 + 2] = v.z; tile[kk][d4 + 3] = v.w;
    }
    __syncthreads();
    #pragma unroll
    for (int i = 0; i < 4; i++) {
        int idx = t + 256 * i;
        int d = idx >> 4, kk4 = (idx & 15) * 4;
        float4 o = make_float4(tile[kk4 + 0][d], tile[kk4 + 1][d],
                               tile[kk4 + 2][d], tile[kk4 + 3][d]);
        uint2 hi, lo; split4(o, hi, lo);
        *(uint2*)&g_vth[((size_t)bh * 64 + d) * 512 + k0 + kk4] = hi;
        *(uint2*)&g_vtl[((size_t)bh * 64 + d) * 512 + k0 + kk4] = lo;
    }
}

// ---------------------------------------------------------------------------
// Flash attention, q-tile 128, 256 threads (8 warps x 16 q-rows),
// 2-stage cp.async pipeline on K/V. fp16-split mma throughout.
// ---------------------------------------------------------------------------
#define QK_STR 136
#define V_STR  72
#define F_QSZ (128*QK_STR)          // 17408 halves per Q buffer
#define F_KSZ (64*QK_STR)           // 8704
#define F_VSZ (64*V_STR)            // 4608
#define F_KBASE (2*F_QSZ)
#define F_VBASE (2*F_QSZ + 4*F_KSZ)
#define F_END   (2*F_QSZ + 4*F_KSZ + 4*F_VSZ)   // halves
#define FLASH_SMEM (F_END*2 + 512*4)            // 178176 B

__device__ __forceinline__ void flash_issue_kv(__half* sh, int stage, int k0,
                                               int bh, int t) {
    __half* Kh = sh + F_KBASE + stage * 2 * F_KSZ;
    __half* Kl = Kh + F_KSZ;
    __half* Vh = sh + F_VBASE + stage * 2 * F_VSZ;
    __half* Vl = Vh + F_VSZ;
    #pragma unroll
    for (int i = 0; i < 4; i++) {
        int c = t + 256 * i;
        int k = c >> 4, seg = (c & 15) * 8;
        size_t g = ((size_t)bh * 512 + k0 + k) * 128 + seg;
        cp16(Kh + k * QK_STR + seg, g_keh + g);
        cp16(Kl + k * QK_STR + seg, g_kel + g);
    }
    #pragma unroll
    for (int i = 0; i < 2; i++) {
        int c = t + 256 * i;
        int d = c >> 3, seg = (c & 7) * 8;
        size_t g = ((size_t)bh * 64 + d) * 512 + k0 + seg;
        cp16(Vh + d * V_STR + seg, g_vth + g);
        cp16(Vl + d * V_STR + seg, g_vtl + g);
    }
}

__global__ __launch_bounds__(256) void flash_attn(const float* __restrict__ mask,
                                                  float* __restrict__ out) {
    extern __shared__ __half sh[];
    __half* Qh = sh;
    __half* Ql = sh + F_QSZ;
    float*  ms = (float*)(sh + F_END);

    int qt = blockIdx.x, bh = blockIdx.y;
    int b = bh >> 4, h = bh & 15;
    int q0 = qt * 128;
    int t = threadIdx.x, lane = t & 31, warp = t >> 5;
    int r = lane >> 2, c2 = (lane & 3) * 2;
    int wq = warp * 16;

    // Q tile via cp.async (group 0, together with first K/V stage)
    #pragma unroll
    for (int i = 0; i < 8; i++) {
        int c = t + 256 * i;
        int q = c >> 4, seg = (c & 15) * 8;
        size_t g = ((size_t)bh * 512 + q0 + q) * 128 + seg;
        cp16(Qh + q * QK_STR + seg, g_qeh + g);
        cp16(Ql + q * QK_STR + seg, g_qel + g);
    }
    flash_issue_kv(sh, 0, 0, bh, t);
    CP_COMMIT;

    ms[t] = mask[b * 512 + t];
    ms[t + 256] = mask[b * 512 + t + 256];

    float m_run[2] = {-1e30f, -1e30f}, l_run[2] = {0.f, 0.f};
    float o[8][4];
    #pragma unroll
    for (int nt = 0; nt < 8; nt++)
        #pragma unroll
        for (int j = 0; j < 4; j++) o[nt][j] = 0.f;

    for (int it = 0; it < 8; it++) {
        if (it < 7) {
            flash_issue_kv(sh, (it + 1) & 1, (it + 1) * 64, bh, t);
            CP_COMMIT;
            CP_WAIT1;
        } else {
            CP_WAIT0;
        }
        __syncthreads();

        const __half* Kh = sh + F_KBASE + (it & 1) * 2 * F_KSZ;
        const __half* Kl = Kh + F_KSZ;
        const __half* Vh = sh + F_VBASE + (it & 1) * 2 * F_VSZ;
        const __half* Vl = Vh + F_VSZ;
        int k0 = it * 64;

        // ---- S = Qe . Ke^T ----
        float s[8][4];
        #pragma unroll
        for (int nt = 0; nt < 8; nt++)
            #pragma unroll
            for (int j = 0; j < 4; j++) s[nt][j] = 0.f;

        #pragma unroll
        for (int st = 0; st < 8; st++) {
            int qq = wq + r;
            uint32_t ah[4], al[4];
            ah[0] = *(const uint32_t*)&Qh[qq * QK_STR + st * 16 + c2];
            ah[1] = *(const uint32_t*)&Qh[(qq + 8) * QK_STR + st * 16 + c2];
            ah[2] = *(const uint32_t*)&Qh[qq * QK_STR + st * 16 + 8 + c2];
            ah[3] = *(const uint32_t*)&Qh[(qq + 8) * QK_STR + st * 16 + 8 + c2];
            al[0] = *(const uint32_t*)&Ql[qq * QK_STR + st * 16 + c2];
            al[1] = *(const uint32_t*)&Ql[(qq + 8) * QK_STR + st * 16 + c2];
            al[2] = *(const uint32_t*)&Ql[qq * QK_STR + st * 16 + 8 + c2];
            al[3] = *(const uint32_t*)&Ql[(qq + 8) * QK_STR + st * 16 + 8 + c2];
            #pragma unroll
            for (int nt = 0; nt < 8; nt++) {
                int nn = nt * 8 + r;
                uint32_t bhf[2], blf[2];
                bhf[0] = *(const uint32_t*)&Kh[nn * QK_STR + st * 16 + c2];
                bhf[1] = *(const uint32_t*)&Kh[nn * QK_STR + st * 16 + 8 + c2];
                blf[0] = *(const uint32_t*)&Kl[nn * QK_STR + st * 16 + c2];
                blf[1] = *(const uint32_t*)&Kl[nn * QK_STR + st * 16 + 8 + c2];
                mma_f16(s[nt], ah, bhf);
                mma_f16(s[nt], ah, blf);
                mma_f16(s[nt], al, bhf);
            }
        }

        // ---- mask + online softmax ----
        float mnew0 = m_run[0], mnew1 = m_run[1];
        #pragma unroll
        for (int nt = 0; nt < 8; nt++) {
            int kc = k0 + nt * 8 + c2;
            float mk0 = ms[kc], mk1 = ms[kc + 1];
            float v0 = s[nt][0] * mk0; s[nt][0] = (v0 == 0.f) ? -INFINITY : v0;
            float v1 = s[nt][1] * mk1; s[nt][1] = (v1 == 0.f) ? -INFINITY : v1;
            float v2 = s[nt][2] * mk0; s[nt][2] = (v2 == 0.f) ? -INFINITY : v2;
            float v3 = s[nt][3] * mk1; s[nt][3] = (v3 == 0.f) ? -INFINITY : v3;
            mnew0 = fmaxf(mnew0, fmaxf(s[nt][0], s[nt][1]));
            mnew1 = fmaxf(mnew1, fmaxf(s[nt][2], s[nt][3]));
        }
        #pragma unroll
        for (int off = 1; off <= 2; off <<= 1) {
            mnew0 = fmaxf(mnew0, __shfl_xor_sync(0xffffffffu, mnew0, off));
            mnew1 = fmaxf(mnew1, __shfl_xor_sync(0xffffffffu, mnew1, off));
        }
        float corr0 = __expf(m_run[0] - mnew0);
        float corr1 = __expf(m_run[1] - mnew1);
        float ts0 = 0.f, ts1 = 0.f;
        #pragma unroll
        for (int nt = 0; nt < 8; nt++) {
            float p0 = __expf(s[nt][0] - mnew0); s[nt][0] = p0;
            float p1 = __expf(s[nt][1] - mnew0); s[nt][1] = p1;
            float p2 = __expf(s[nt][2] - mnew1); s[nt][2] = p2;
            float p3 = __expf(s[nt][3] - mnew1); s[nt][3] = p3;
            ts0 += p0 + p1; ts1 += p2 + p3;
        }
        #pragma unroll
        for (int off = 1; off <= 2; off <<= 1) {
            ts0 += __shfl_xor_sync(0xffffffffu, ts0, off);
            ts1 += __shfl_xor_sync(0xffffffffu, ts1, off);
        }
        l_run[0] = l_run[0] * corr0 + ts0;
        l_run[1] = l_run[1] * corr1 + ts1;
        m_run[0] = mnew0; m_run[1] = mnew1;
        #pragma unroll
        for (int nt = 0; nt < 8; nt++) {
            o[nt][0] *= corr0; o[nt][1] *= corr0;
            o[nt][2] *= corr1; o[nt][3] *= corr1;
        }

        // ---- O += P . V (P in registers) ----
        #pragma unroll
        for (int s2 = 0; s2 < 4; s2++) {
            float* pa = s[2 * s2];
            float* pb = s[2 * s2 + 1];
            __half h00 = __float2half_rn(pa[0]), h01 = __float2half_rn(pa[1]);
            __half h02 = __float2half_rn(pa[2]), h03 = __float2half_rn(pa[3]);
            __half h10 = __float2half_rn(pb[0]), h11 = __float2half_rn(pb[1]);
            __half h12 = __float2half_rn(pb[2]), h13 = __float2half_rn(pb[3]);
            uint32_t ph[4], pl[4];
            ph[0] = pack2h(h00, h01);
            ph[1] = pack2h(h02, h03);
            ph[2] = pack2h(h10, h11);
            ph[3] = pack2h(h12, h13);
            pl[0] = pack2h(__float2half_rn(pa[0] - __half2float(h00)),
                           __float2half_rn(pa[1] - __half2float(h01)));
            pl[1] = pack2h(__float2half_rn(pa[2] - __half2float(h02)),
                           __float2half_rn(pa[3] - __half2float(h03)));
            pl[2] = pack2h(__float2half_rn(pb[0] - __half2float(h10)),
                           __float2half_rn(pb[1] - __half2float(h11)));
            pl[3] = pack2h(__float2half_rn(pb[2] - __half2float(h12)),
                           __float2half_rn(pb[3] - __half2float(h13)));
            #pragma unroll
            for (int ntd = 0; ntd < 8; ntd++) {
                int dd = ntd * 8 + r;
                uint32_t bhf[2], blf[2];
                bhf[0] = *(const uint32_t*)&Vh[dd * V_STR + s2 * 16 + c2];
                bhf[1] = *(const uint32_t*)&Vh[dd * V_STR + s2 * 16 + 8 + c2];
                blf[0] = *(const uint32_t*)&Vl[dd * V_STR + s2 * 16 + c2];
                blf[1] = *(const uint32_t*)&Vl[dd * V_STR + s2 * 16 + 8 + c2];
                mma_f16(o[ntd], ph, bhf);
                mma_f16(o[ntd], ph, blf);
                mma_f16(o[ntd], pl, bhf);
            }
        }
        __syncthreads();
    }

    // ---- finalize ----
    float inv0 = 1.0f / l_run[0], inv1 = 1.0f / l_run[1];
    int qg0 = q0 + wq + r;
    #pragma unroll
    for (int ntd = 0; ntd < 8; ntd++) {
        int d = ntd * 8 + c2;
        *(float2*)&out[((size_t)(b * 512) + qg0) * 1024 + h * 64 + d] =
            make_float2(o[ntd][0] * inv0, o[ntd][1] * inv0);
        *(float2*)&out[((size_t)(b * 512) + qg0 + 8) * 1024 + h * 64 + d] =
            make_float2(o[ntd][2] * inv1, o[ntd][3] * inv1);
    }
}

// ---------------------------------------------------------------------------
extern "C" void kernel_launch(void* const* d_in, const int* in_sizes, int n_in,
                              void* d_out, int out_size) {
    const float* x    = (const float*)d_in[0];
    const float* mask = (const float*)d_in[1];
    const float* W    = (const float*)d_in[2];
    const float* rr   = (const float*)d_in[3];
    const float* rw   = (const float*)d_in[4];
    float* out = (float*)d_out;

    cudaFuncSetAttribute(qv_gemm_f16, cudaFuncAttributeMaxDynamicSharedMemorySize,
                         QV_SMEM);
    cudaFuncSetAttribute(flash_attn, cudaFuncAttributeMaxDynamicSharedMemorySize,
                         FLASH_SMEM);

    rot_kernel<<<512, 64>>>();
    prep_x<<<4096, 256>>>(x);
    prep_w<<<dim3(64, 32), 256>>>(W);
    qv_gemm_f16<<<dim3(16, 32), 256, QV_SMEM>>>();
    qe_build<<<dim3(128, 128), 256>>>(rr, rw);
    ke_build<<<dim3(128, 8), 256>>>(x);
    build_vt<<<dim3(128, 8), 256>>>();
    flash_attn<<<dim3(4, 128), 256, FLASH_SMEM>>>(mask, out);
}

// round 8
// speedup vs baseline: 2.8384x; 1.0505x over previous
#include <cuda_runtime.h>
#include <cuda_fp16.h>
#include <math.h>
#include <stdint.h>

#define BB 8
#define LL 512
#define DM 1024
#define NH 16
#define HD 64
#define BH (BB*NH)     // 128

// ---- scratch (device globals; allocation-free rule) ----
__device__ float  g_q  [(size_t)BH*LL*HD];
__device__ float  g_v  [(size_t)BH*LL*HD];
__device__ float  g_rot[(size_t)LL*64];
__device__ __align__(16) __half g_xh [(size_t)4096*1024];
__device__ __align__(16) __half g_xl [(size_t)4096*1024];
__device__ __align__(16) __half g_wth[(size_t)2048*1024];
__device__ __align__(16) __half g_wtl[(size_t)2048*1024];
__device__ __align__(16) __half g_qeh[(size_t)BH*LL*128];
__device__ __align__(16) __half g_qel[(size_t)BH*LL*128];
__device__ __align__(16) __half g_keh[(size_t)BH*LL*128];
__device__ __align__(16) __half g_kel[(size_t)BH*LL*128];
__device__ __align__(16) __half g_vth[(size_t)BH*HD*LL];
__device__ __align__(16) __half g_vtl[(size_t)BH*HD*LL];

// ---------------------------------------------------------------------------
__device__ __forceinline__ uint32_t pack2h(__half a, __half b) {
    __half2 p = __halves2half2(a, b);
    return *reinterpret_cast<uint32_t*>(&p);
}
__device__ __forceinline__ void split4(float4 v, uint2& hi, uint2& lo) {
    __half h0 = __float2half_rn(v.x), h1 = __float2half_rn(v.y);
    __half h2 = __float2half_rn(v.z), h3 = __float2half_rn(v.w);
    hi.x = pack2h(h0, h1); hi.y = pack2h(h2, h3);
    lo.x = pack2h(__float2half_rn(v.x - __half2float(h0)),
                  __float2half_rn(v.y - __half2float(h1)));
    lo.y = pack2h(__float2half_rn(v.z - __half2float(h2)),
                  __float2half_rn(v.w - __half2float(h3)));
}
__device__ __forceinline__ void mma_f16(float* c, const uint32_t* a, const uint32_t* b) {
    asm volatile(
        "mma.sync.aligned.m16n8k16.row.col.f32.f16.f16.f32 "
        "{%0,%1,%2,%3}, {%4,%5,%6,%7}, {%8,%9}, {%0,%1,%2,%3};\n"
        : "+f"(c[0]), "+f"(c[1]), "+f"(c[2]), "+f"(c[3])
        : "r"(a[0]), "r"(a[1]), "r"(a[2]), "r"(a[3]), "r"(b[0]), "r"(b[1]));
}
__device__ __forceinline__ void ldsm4(uint32_t* r, uint32_t addr) {
    asm volatile("ldmatrix.sync.aligned.m8n8.x4.shared.b16 {%0,%1,%2,%3}, [%4];"
                 : "=r"(r[0]), "=r"(r[1]), "=r"(r[2]), "=r"(r[3]) : "r"(addr));
}
__device__ __forceinline__ uint32_t smem_u32(const void* p) {
    return (uint32_t)__cvta_generic_to_shared(p);
}
__device__ __forceinline__ void cp16(void* dst, const void* src) {
    uint32_t s = (uint32_t)__cvta_generic_to_shared(dst);
    asm volatile("cp.async.cg.shared.global [%0], [%1], 16;\n" :: "r"(s), "l"(src));
}
#define CP_COMMIT asm volatile("cp.async.commit_group;\n")
#define CP_WAIT1  asm volatile("cp.async.wait_group 1;\n")
#define CP_WAIT0  asm volatile("cp.async.wait_group 0;\n")

// ---------------------------------------------------------------------------
__global__ void rot_kernel() {
    int k = blockIdx.x, d = threadIdx.x;
    int i = d & 31;
    float w = expf(-(float)i * (logf(10000.0f) / 31.0f));
    float ang = (float)k * w;
    g_rot[k * 64 + d] = (d < 32) ? sinf(ang) : cosf(ang);
}

__global__ __launch_bounds__(256) void prep_x(const float* __restrict__ X) {
    int idx = blockIdx.x * 256 + threadIdx.x;
    float4 v = ((const float4*)X)[idx];
    uint2 hi, lo; split4(v, hi, lo);
    ((uint2*)g_xh)[idx] = hi;
    ((uint2*)g_xl)[idx] = lo;
}

__global__ __launch_bounds__(256) void prep_w(const float* __restrict__ W) {
    __shared__ float tile[32][33];
    int n0 = blockIdx.x * 32, k0 = blockIdx.y * 32;
    int t = threadIdx.x;
    int row = t >> 3, c4 = (t & 7) * 4;
    float4 v = *(const float4*)&W[(size_t)(k0 + row) * 2048 + n0 + c4];
    tile[row][c4 + 0] = v.x; tile[row][c4 + 1] = v.y;
    tile[row][c4 + 2] = v.z; tile[row][c4 + 3] = v.w;
    __syncthreads();
    float4 o = make_float4(tile[c4 + 0][row], tile[c4 + 1][row],
                           tile[c4 + 2][row], tile[c4 + 3][row]);
    uint2 hi, lo; split4(o, hi, lo);
    *(uint2*)&g_wth[(size_t)(n0 + row) * 1024 + k0 + c4] = hi;
    *(uint2*)&g_wtl[(size_t)(n0 + row) * 1024 + k0 + c4] = lo;
}

// ---------------------------------------------------------------------------
// qv GEMM, fp16-split mma + ldmatrix fragment loads + 2-stage cp.async.
// C = X @ W, M=4096, N=2048, K=1024. 128x128 tile, BK=32, 8 warps (4x2).
// ---------------------------------------------------------------------------
#define QV_PS (128*40)        // halves per buffer
#define QV_SS (4*QV_PS)       // halves per stage (Ah,Al,Bh,Bl)
#define QV_SMEM (2*QV_SS*2)   // bytes = 81920

__device__ __forceinline__ void qv_issue(__half* qsm, int stage, int k0,
                                         int m0, int n0, int t) {
    __half* base = qsm + stage * QV_SS;
    #pragma unroll
    for (int i = 0; i < 2; i++) {
        int c = t + 256 * i;
        int row = c >> 2, seg = (c & 3) * 8;
        size_t ga = (size_t)(m0 + row) * 1024 + k0 + seg;
        size_t gb = (size_t)(n0 + row) * 1024 + k0 + seg;
        cp16(base + row * 40 + seg,               g_xh  + ga);
        cp16(base + QV_PS + row * 40 + seg,       g_xl  + ga);
        cp16(base + 2 * QV_PS + row * 40 + seg,   g_wth + gb);
        cp16(base + 3 * QV_PS + row * 40 + seg,   g_wtl + gb);
    }
}

__global__ __launch_bounds__(256) void qv_gemm_f16() {
    extern __shared__ __half qsm[];
    int t = threadIdx.x, lane = t & 31, warp = t >> 5;
    int m0 = blockIdx.y * 128, n0 = blockIdx.x * 128;
    int wm = (warp >> 1) * 32, wn = (warp & 1) * 64;
    int r = lane >> 2, c2 = (lane & 3) * 2;

    // ldmatrix per-thread offsets (bytes)
    int lane7 = lane & 7;
    int lrow = lane7 + ((lane >> 3) & 1) * 8;     // row within m16 tile
    int acol = ((lane >> 4) & 1) * 8;             // k-half (0 or 8)
    uint32_t offA0 = ((wm + lrow) * 40 + acol) * 2;
    uint32_t offA1 = ((wm + 16 + lrow) * 40 + acol) * 2;
    int brow = ((lane >> 4) & 1) * 8 + lane7;     // row within n16 pair
    int bcol = ((lane >> 3) & 1) * 8;
    uint32_t offB[4];
    #pragma unroll
    for (int j = 0; j < 4; j++) offB[j] = ((wn + j * 16 + brow) * 40 + bcol) * 2;
    uint32_t sQ = smem_u32(qsm);

    float acc[2][8][4];
    #pragma unroll
    for (int mt = 0; mt < 2; mt++)
        #pragma unroll
        for (int nt = 0; nt < 8; nt++)
            #pragma unroll
            for (int j = 0; j < 4; j++) acc[mt][nt][j] = 0.f;

    qv_issue(qsm, 0, 0, m0, n0, t);
    CP_COMMIT;

    for (int it = 0; it < 32; it++) {
        if (it < 31) {
            qv_issue(qsm, (it + 1) & 1, (it + 1) * 32, m0, n0, t);
            CP_COMMIT;
            CP_WAIT1;
        } else {
            CP_WAIT0;
        }
        __syncthreads();

        uint32_t stB = sQ + (it & 1) * (QV_SS * 2);
        uint32_t aH = stB;
        uint32_t aL = stB + QV_PS * 2;
        uint32_t bH = stB + 2 * QV_PS * 2;
        uint32_t bL = stB + 3 * QV_PS * 2;

        #pragma unroll
        for (int s = 0; s < 2; s++) {
            uint32_t ah0[4], ah1[4], al0[4], al1[4];
            ldsm4(ah0, aH + offA0 + s * 32);
            ldsm4(ah1, aH + offA1 + s * 32);
            ldsm4(al0, aL + offA0 + s * 32);
            ldsm4(al1, aL + offA1 + s * 32);
            #pragma unroll
            for (int j = 0; j < 4; j++) {
                uint32_t b_h[4], b_l[4];
                ldsm4(b_h, bH + offB[j] + s * 32);
                ldsm4(b_l, bL + offB[j] + s * 32);
                mma_f16(acc[0][2 * j],     ah0, &b_h[0]);
                mma_f16(acc[1][2 * j],     ah1, &b_h[0]);
                mma_f16(acc[0][2 * j],     ah0, &b_l[0]);
                mma_f16(acc[1][2 * j],     ah1, &b_l[0]);
                mma_f16(acc[0][2 * j],     al0, &b_h[0]);
                mma_f16(acc[1][2 * j],     al1, &b_h[0]);
                mma_f16(acc[0][2 * j + 1], ah0, &b_h[2]);
                mma_f16(acc[1][2 * j + 1], ah1, &b_h[2]);
                mma_f16(acc[0][2 * j + 1], ah0, &b_l[2]);
                mma_f16(acc[1][2 * j + 1], ah1, &b_l[2]);
                mma_f16(acc[0][2 * j + 1], al0, &b_h[2]);
                mma_f16(acc[1][2 * j + 1], al1, &b_h[2]);
            }
        }
        __syncthreads();
    }

    #pragma unroll
    for (int mt = 0; mt < 2; mt++) {
        #pragma unroll
        for (int nt = 0; nt < 8; nt++) {
            int r0 = m0 + wm + mt * 16 + r;
            int cc = n0 + wn + nt * 8 + c2;
            #pragma unroll
            for (int half_ = 0; half_ < 2; half_++) {
                int m = r0 + half_ * 8;
                float2 val = make_float2(acc[mt][nt][half_ * 2],
                                         acc[mt][nt][half_ * 2 + 1]);
                int bi = m >> 9, l = m & 511;
                if (cc < 1024) {
                    int h = cc >> 6, d = cc & 63;
                    *(float2*)&g_q[(((size_t)(bi * 16 + h) * 512) + l) * 64 + d] = val;
                } else {
                    int n2 = cc - 1024;
                    int h = n2 >> 6, d = n2 & 63;
                    *(float2*)&g_v[(((size_t)(bi * 16 + h) * 512) + l) * 64 + d] = val;
                }
            }
        }
    }
}

// ---------------------------------------------------------------------------
__global__ __launch_bounds__(256) void qe_build(const float* __restrict__ rr,
                                                const float* __restrict__ rw) {
    __shared__ float u[4][64];
    int bh = blockIdx.x, h = bh & 15;
    int row = threadIdx.x >> 6;
    int d = threadIdx.x & 63;
    int q = blockIdx.y * 4 + row;

    float qv = g_q[((size_t)bh * 512 + q) * 64 + d];
    float outA = qv + rr[h * 64 + d];
    float uu = qv + rw[h * 64 + d];
    u[row][d] = uu;
    __syncthreads();
    int i = d & 31;
    float sq = g_rot[q * 64 + i];
    float cq = g_rot[q * 64 + 32 + i];
    float partner = u[row][d ^ 32];
    float outB = uu * cq + ((d < 32) ? partner : -partner) * sq;

    size_t base = ((size_t)bh * 512 + q) * 128;
    __half ha = __float2half_rn(outA);
    __half hb = __float2half_rn(outB);
    g_qeh[base + d] = ha;
    g_qeh[base + 64 + d] = hb;
    g_qel[base + d] = __float2half_rn(outA - __half2float(ha));
    g_qel[base + 64 + d] = __float2half_rn(outB - __half2float(hb));
}

__global__ __launch_bounds__(256) void ke_build(const float* __restrict__ X) {
    int bh = blockIdx.x;
    int b = bh >> 4, h = bh & 15;
    int kbase = blockIdx.y * 64;
    for (int i = threadIdx.x; i < 64 * 128; i += 256) {
        int k = kbase + (i >> 7), c = i & 127;
        float f = (c < 64) ? X[((size_t)(b * 512) + k) * 1024 + h * 64 + c]
                           : g_rot[k * 64 + (c - 64)];
        __half hi = __float2half_rn(f);
        size_t o = ((size_t)bh * 512 + k) * 128 + c;
        g_keh[o] = hi;
        g_kel[o] = __float2half_rn(f - __half2float(hi));
    }
}

__global__ __launch_bounds__(256) void build_vt() {
    __shared__ float tile[64][65];
    int bh = blockIdx.x;
    int k0 = blockIdx.y * 64;
    int t = threadIdx.x;
    #pragma unroll
    for (int i = 0; i < 4; i++) {
        int idx = t + 256 * i;
        int kk = idx >> 4, d4 = (idx & 15) * 4;
        float4 v = *(const float4*)&g_v[((size_t)bh * 512 + k0 + kk) * 64 + d4];
        tile[kk][d4 + 0] = v.x; tile[kk][d4 + 1] = v.y;
        tile[kk][d4 + 2] = v.z; tile[kk][d4 + 3] = v.w;
    }
    __syncthreads();
    #pragma unroll
    for (int i = 0; i < 4; i++) {
        int idx = t + 256 * i;
        int d = idx >> 4, kk4 = (idx & 15) * 4;
        float4 o = make_float4(tile[kk4 + 0][d], tile[kk4 + 1][d],
                               tile[kk4 + 2][d], tile[kk4 + 3][d]);
        uint2 hi, lo; split4(o, hi, lo);
        *(uint2*)&g_vth[((size_t)bh * 64 + d) * 512 + k0 + kk4] = hi;
        *(uint2*)&g_vtl[((size_t)bh * 64 + d) * 512 + k0 + kk4] = lo;
    }
}

// ---------------------------------------------------------------------------
// Flash attention, q-tile 128, 256 threads, 2-stage cp.async K/V,
// ldmatrix fragment loads, Q fragments hoisted into registers.
// ---------------------------------------------------------------------------
#define QK_STR 136
#define V_STR  72
#define F_QSZ (128*QK_STR)
#define F_KSZ (64*QK_STR)
#define F_VSZ (64*V_STR)
#define F_KBASE (2*F_QSZ)
#define F_VBASE (2*F_QSZ + 4*F_KSZ)
#define F_END   (2*F_QSZ + 4*F_KSZ + 4*F_VSZ)
#define FLASH_SMEM (F_END*2 + 512*4)

__device__ __forceinline__ void flash_issue_kv(__half* sh, int stage, int k0,
                                               int bh, int t) {
    __half* Kh = sh + F_KBASE + stage * 2 * F_KSZ;
    __half* Kl = Kh + F_KSZ;
    __half* Vh = sh + F_VBASE + stage * 2 * F_VSZ;
    __half* Vl = Vh + F_VSZ;
    #pragma unroll
    for (int i = 0; i < 4; i++) {
        int c = t + 256 * i;
        int k = c >> 4, seg = (c & 15) * 8;
        size_t g = ((size_t)bh * 512 + k0 + k) * 128 + seg;
        cp16(Kh + k * QK_STR + seg, g_keh + g);
        cp16(Kl + k * QK_STR + seg, g_kel + g);
    }
    #pragma unroll
    for (int i = 0; i < 2; i++) {
        int c = t + 256 * i;
        int d = c >> 3, seg = (c & 7) * 8;
        size_t g = ((size_t)bh * 64 + d) * 512 + k0 + seg;
        cp16(Vh + d * V_STR + seg, g_vth + g);
        cp16(Vl + d * V_STR + seg, g_vtl + g);
    }
}

__global__ __launch_bounds__(256) void flash_attn(const float* __restrict__ mask,
                                                  float* __restrict__ out) {
    extern __shared__ __half sh[];
    float* ms = (float*)(sh + F_END);

    int qt = blockIdx.x, bh = blockIdx.y;
    int b = bh >> 4, h = bh & 15;
    int q0 = qt * 128;
    int t = threadIdx.x, lane = t & 31, warp = t >> 5;
    int r = lane >> 2, c2 = (lane & 3) * 2;
    int wq = warp * 16;

    // ldmatrix offsets
    int lane7 = lane & 7;
    int lrow = lane7 + ((lane >> 3) & 1) * 8;
    int acol = ((lane >> 4) & 1) * 8;
    uint32_t offQ = ((wq + lrow) * QK_STR + acol) * 2;
    int brow = ((lane >> 4) & 1) * 8 + lane7;
    int bcol = ((lane >> 3) & 1) * 8;
    uint32_t offK[4], offV[4];
    #pragma unroll
    for (int j = 0; j < 4; j++) {
        offK[j] = ((j * 16 + brow) * QK_STR + bcol) * 2;
        offV[j] = ((j * 16 + brow) * V_STR + bcol) * 2;
    }
    uint32_t sF = smem_u32(sh);

    // Q tile + first KV stage via cp.async (one commit group)
    #pragma unroll
    for (int i = 0; i < 8; i++) {
        int c = t + 256 * i;
        int q = c >> 4, seg = (c & 15) * 8;
        size_t g = ((size_t)bh * 512 + q0 + q) * 128 + seg;
        cp16(sh + q * QK_STR + seg, g_qeh + g);
        cp16(sh + F_QSZ + q * QK_STR + seg, g_qel + g);
    }
    flash_issue_kv(sh, 0, 0, bh, t);
    CP_COMMIT;

    ms[t] = mask[b * 512 + t];
    ms[t + 256] = mask[b * 512 + t + 256];

    float m_run[2] = {-1e30f, -1e30f}, l_run[2] = {0.f, 0.f};
    float o[8][4];
    #pragma unroll
    for (int nt = 0; nt < 8; nt++)
        #pragma unroll
        for (int j = 0; j < 4; j++) o[nt][j] = 0.f;

    uint32_t qh[8][4], ql[8][4];   // hoisted Q fragments

    for (int it = 0; it < 8; it++) {
        if (it < 7) {
            flash_issue_kv(sh, (it + 1) & 1, (it + 1) * 64, bh, t);
            CP_COMMIT;
            CP_WAIT1;
        } else {
            CP_WAIT0;
        }
        __syncthreads();

        if (it == 0) {
            #pragma unroll
            for (int st = 0; st < 8; st++) {
                ldsm4(qh[st], sF + offQ + st * 32);
                ldsm4(ql[st], sF + F_QSZ * 2 + offQ + st * 32);
            }
        }

        uint32_t aKh = sF + (F_KBASE + (it & 1) * 2 * F_KSZ) * 2;
        uint32_t aKl = aKh + F_KSZ * 2;
        uint32_t aVh = sF + (F_VBASE + (it & 1) * 2 * F_VSZ) * 2;
        uint32_t aVl = aVh + F_VSZ * 2;
        int k0 = it * 64;

        // ---- S = Qe . Ke^T ----
        float s[8][4];
        #pragma unroll
        for (int nt = 0; nt < 8; nt++)
            #pragma unroll
            for (int j = 0; j < 4; j++) s[nt][j] = 0.f;

        #pragma unroll
        for (int st = 0; st < 8; st++) {
            #pragma unroll
            for (int j = 0; j < 4; j++) {
                uint32_t kh4[4], kl4[4];
                ldsm4(kh4, aKh + offK[j] + st * 32);
                ldsm4(kl4, aKl + offK[j] + st * 32);
                mma_f16(s[2 * j],     qh[st], &kh4[0]);
                mma_f16(s[2 * j],     qh[st], &kl4[0]);
                mma_f16(s[2 * j],     ql[st], &kh4[0]);
                mma_f16(s[2 * j + 1], qh[st], &kh4[2]);
                mma_f16(s[2 * j + 1], qh[st], &kl4[2]);
                mma_f16(s[2 * j + 1], ql[st], &kh4[2]);
            }
        }

        // ---- mask + online softmax ----
        float mnew0 = m_run[0], mnew1 = m_run[1];
        #pragma unroll
        for (int nt = 0; nt < 8; nt++) {
            int kc = k0 + nt * 8 + c2;
            float mk0 = ms[kc], mk1 = ms[kc + 1];
            float v0 = s[nt][0] * mk0; s[nt][0] = (v0 == 0.f) ? -INFINITY : v0;
            float v1 = s[nt][1] * mk1; s[nt][1] = (v1 == 0.f) ? -INFINITY : v1;
            float v2 = s[nt][2] * mk0; s[nt][2] = (v2 == 0.f) ? -INFINITY : v2;
            float v3 = s[nt][3] * mk1; s[nt][3] = (v3 == 0.f) ? -INFINITY : v3;
            mnew0 = fmaxf(mnew0, fmaxf(s[nt][0], s[nt][1]));
            mnew1 = fmaxf(mnew1, fmaxf(s[nt][2], s[nt][3]));
        }
        #pragma unroll
        for (int off = 1; off <= 2; off <<= 1) {
            mnew0 = fmaxf(mnew0, __shfl_xor_sync(0xffffffffu, mnew0, off));
            mnew1 = fmaxf(mnew1, __shfl_xor_sync(0xffffffffu, mnew1, off));
        }
        float corr0 = __expf(m_run[0] - mnew0);
        float corr1 = __expf(m_run[1] - mnew1);
        float ts0 = 0.f, ts1 = 0.f;
        #pragma unroll
        for (int nt = 0; nt < 8; nt++) {
            float p0 = __expf(s[nt][0] - mnew0); s[nt][0] = p0;
            float p1 = __expf(s[nt][1] - mnew0); s[nt][1] = p1;
            float p2 = __expf(s[nt][2] - mnew1); s[nt][2] = p2;
            float p3 = __expf(s[nt][3] - mnew1); s[nt][3] = p3;
            ts0 += p0 + p1; ts1 += p2 + p3;
        }
        #pragma unroll
        for (int off = 1; off <= 2; off <<= 1) {
            ts0 += __shfl_xor_sync(0xffffffffu, ts0, off);
            ts1 += __shfl_xor_sync(0xffffffffu, ts1, off);
        }
        l_run[0] = l_run[0] * corr0 + ts0;
        l_run[1] = l_run[1] * corr1 + ts1;
        m_run[0] = mnew0; m_run[1] = mnew1;
        #pragma unroll
        for (int nt = 0; nt < 8; nt++) {
            o[nt][0] *= corr0; o[nt][1] *= corr0;
            o[nt][2] *= corr1; o[nt][3] *= corr1;
        }

        // ---- O += P . V (P in registers) ----
        #pragma unroll
        for (int s2 = 0; s2 < 4; s2++) {
            float* pa = s[2 * s2];
            float* pb = s[2 * s2 + 1];
            __half h00 = __float2half_rn(pa[0]), h01 = __float2half_rn(pa[1]);
            __half h02 = __float2half_rn(pa[2]), h03 = __float2half_rn(pa[3]);
            __half h10 = __float2half_rn(pb[0]), h11 = __float2half_rn(pb[1]);
            __half h12 = __float2half_rn(pb[2]), h13 = __float2half_rn(pb[3]);
            uint32_t ph[4], pl[4];
            ph[0] = pack2h(h00, h01);
            ph[1] = pack2h(h02, h03);
            ph[2] = pack2h(h10, h11);
            ph[3] = pack2h(h12, h13);
            pl[0] = pack2h(__float2half_rn(pa[0] - __half2float(h00)),
                           __float2half_rn(pa[1] - __half2float(h01)));
            pl[1] = pack2h(__float2half_rn(pa[2] - __half2float(h02)),
                           __float2half_rn(pa[3] - __half2float(h03)));
            pl[2] = pack2h(__float2half_rn(pb[0] - __half2float(h10)),
                           __float2half_rn(pb[1] - __half2float(h11)));
            pl[3] = pack2h(__float2half_rn(pb[2] - __half2float(h12)),
                           __float2half_rn(pb[3] - __half2float(h13)));
            #pragma unroll
            for (int j = 0; j < 4; j++) {
                uint32_t vh4[4], vl4[4];
                ldsm4(vh4, aVh + offV[j] + s2 * 32);
                ldsm4(vl4, aVl + offV[j] + s2 * 32);
                mma_f16(o[2 * j],     ph, &vh4[0]);
                mma_f16(o[2 * j],     ph, &vl4[0]);
                mma_f16(o[2 * j],     pl, &vh4[0]);
                mma_f16(o[2 * j + 1], ph, &vh4[2]);
                mma_f16(o[2 * j + 1], ph, &vl4[2]);
                mma_f16(o[2 * j + 1], pl, &vh4[2]);
            }
        }
        __syncthreads();
    }

    float inv0 = 1.0f / l_run[0], inv1 = 1.0f / l_run[1];
    int qg0 = q0 + wq + r;
    #pragma unroll
    for (int ntd = 0; ntd < 8; ntd++) {
        int d = ntd * 8 + c2;
        *(float2*)&out[((size_t)(b * 512) + qg0) * 1024 + h * 64 + d] =
            make_float2(o[ntd][0] * inv0, o[ntd][1] * inv0);
        *(float2*)&out[((size_t)(b * 512) + qg0 + 8) * 1024 + h * 64 + d] =
            make_float2(o[ntd][2] * inv1, o[ntd][3] * inv1);
    }
}

// ---------------------------------------------------------------------------
extern "C" void kernel_launch(void* const* d_in, const int* in_sizes, int n_in,
                              void* d_out, int out_size) {
    const float* x    = (const float*)d_in[0];
    const float* mask = (const float*)d_in[1];
    const float* W    = (const float*)d_in[2];
    const float* rr   = (const float*)d_in[3];
    const float* rw   = (const float*)d_in[4];
    float* out = (float*)d_out;

    cudaFuncSetAttribute(qv_gemm_f16, cudaFuncAttributeMaxDynamicSharedMemorySize,
                         QV_SMEM);
    cudaFuncSetAttribute(flash_attn, cudaFuncAttributeMaxDynamicSharedMemorySize,
                         FLASH_SMEM);

    rot_kernel<<<512, 64>>>();
    prep_x<<<4096, 256>>>(x);
    prep_w<<<dim3(64, 32), 256>>>(W);
    qv_gemm_f16<<<dim3(16, 32), 256, QV_SMEM>>>();
    qe_build<<<dim3(128, 128), 256>>>(rr, rw);
    ke_build<<<dim3(128, 8), 256>>>(x);
    build_vt<<<dim3(128, 8), 256>>>();
    flash_attn<<<dim3(4, 128), 256, FLASH_SMEM>>>(mask, out);
}